// round 1
// baseline (speedup 1.0000x reference)
#include <cuda_runtime.h>
#include <math.h>

#define TT 12
#define NN 20000
#define EE 400000
#define FF 32
#define HH 64
#define OO 8

// Output layout (flattened tuple): out[4,N,8] | c2[N,64] | emb[T,N,64]
#define OUT_OFF 0
#define C2_OFF  (4*NN*OO)                 // 640000
#define EMB_OFF (C2_OFF + NN*HH)          // 1920000

// ---------------- scratch (static device globals; allocation-free at runtime) ----
__device__ int   g_rowptr[NN + 1];
__device__ int   g_cursor[NN];
__device__ int   g_csr_src[EE];
__device__ float g_csr_w[EE];
__device__ float g_xr[TT * NN * HH];          // relu(emb)
__device__ float g_aggx[TT * NN * FF];        // wmean(x) per t
__device__ float g_aggxr[TT * NN * HH];       // wmean(xr) per t
__device__ float g_pre[2][TT * NN * 4 * HH];  // precomputed gate contributions per LSTM
__device__ float g_h[2][NN * HH];             // ping-pong hidden state
__device__ float g_c[NN * HH];
__device__ float g_aggh[NN * HH];
__device__ float g_h2last[4 * NN * HH];       // h2 for last 4 steps

// ---------------- CSR construction ------------------------------------------------
__global__ void k_zero_cursor() {
    int i = blockIdx.x * blockDim.x + threadIdx.x;
    if (i < NN) g_cursor[i] = 0;
}

__global__ void k_deg(const int* __restrict__ dst) {
    int e = blockIdx.x * blockDim.x + threadIdx.x;
    if (e < EE) atomicAdd(&g_cursor[dst[e]], 1);
}

// Single-block exclusive scan of g_cursor (N=20000) -> g_rowptr, and reset cursor to row start.
__global__ void k_scan() {
    __shared__ int wsum[32];
    const int CH = 20;  // 1024 * 20 = 20480 >= 20000
    int tid = threadIdx.x;
    int base = tid * CH;
    int loc[CH];
    int s = 0;
#pragma unroll
    for (int i = 0; i < CH; i++) {
        int idx = base + i;
        int v = (idx < NN) ? g_cursor[idx] : 0;
        loc[i] = s;
        s += v;
    }
    int lane = tid & 31, w = tid >> 5;
    int inc = s;
#pragma unroll
    for (int o = 1; o < 32; o <<= 1) {
        int t = __shfl_up_sync(0xffffffffu, inc, o);
        if (lane >= o) inc += t;
    }
    if (lane == 31) wsum[w] = inc;
    __syncthreads();
    if (w == 0) {
        int v = wsum[lane];
#pragma unroll
        for (int o = 1; o < 32; o <<= 1) {
            int t = __shfl_up_sync(0xffffffffu, v, o);
            if (lane >= o) v += t;
        }
        wsum[lane] = v;
    }
    __syncthreads();
    int excl = inc - s + (w > 0 ? wsum[w - 1] : 0);
#pragma unroll
    for (int i = 0; i < CH; i++) {
        int idx = base + i;
        if (idx < NN) {
            int p = excl + loc[i];
            g_rowptr[idx] = p;
            g_cursor[idx] = p;
        }
    }
    if (tid == 0) g_rowptr[NN] = EE;
}

__global__ void k_fill(const int* __restrict__ src, const int* __restrict__ dst,
                       const float* __restrict__ ew) {
    int e = blockIdx.x * blockDim.x + threadIdx.x;
    if (e < EE) {
        int d = dst[e];
        int pos = atomicAdd(&g_cursor[d], 1);
        g_csr_src[pos] = src[e];
        g_csr_w[pos] = ew[e];
    }
}

// ---------------- weighted-mean aggregation (CSR, warp per node) ------------------
// mode 0: in = xin + t*N*FD  -> g_aggx   (FD=32)
// mode 1: in = g_xr + t*N*FD -> g_aggxr  (FD=64)
// mode 2: in = g_h[parity]   -> g_aggh   (FD=64, single t)
template <int FD>
__global__ void k_agg(int mode, int parity, const float* __restrict__ xin) {
    int gw = (blockIdx.x * blockDim.x + threadIdx.x) >> 5;
    int lane = threadIdx.x & 31;
    if (gw >= NN) return;
    size_t toff = (size_t)blockIdx.y * NN * FD;
    const float* __restrict__ in;
    float* __restrict__ out;
    if (mode == 0) { in = xin + toff;   out = g_aggx + toff; }
    else if (mode == 1) { in = g_xr + toff; out = g_aggxr + toff; }
    else { in = g_h[parity]; out = g_aggh; }

    int e0 = g_rowptr[gw], e1 = g_rowptr[gw + 1];
    float acc[FD / 32];
#pragma unroll
    for (int i = 0; i < FD / 32; i++) acc[i] = 0.f;
    for (int e = e0; e < e1; e++) {
        int s = __ldg(&g_csr_src[e]);
        float w = __ldg(&g_csr_w[e]);
#pragma unroll
        for (int i = 0; i < FD / 32; i++)
            acc[i] += w * __ldg(&in[(size_t)s * FD + lane + 32 * i]);
    }
    float inv = 1.f / (float)max(e1 - e0, 1);
#pragma unroll
    for (int i = 0; i < FD / 32; i++)
        out[(size_t)gw * FD + lane + 32 * i] = acc[i] * inv;
}

// ---------------- SAGE: emb = aggx@Wr + x@Wroot + b ; xr = relu(emb) --------------
// M = T*N = 240000 (divisible by 64), K = 32+32, Nout = 64. Tile 64x64, 256 threads.
__global__ __launch_bounds__(256) void k_sage(const float* __restrict__ x,
                                              const float* __restrict__ Wr,
                                              const float* __restrict__ Wroot,
                                              const float* __restrict__ b,
                                              float* __restrict__ emb) {
    __shared__ float sA[64][33];
    __shared__ float sW[32][65];
    int m0 = blockIdx.x * 64;
    int tid = threadIdx.x;
    int tr = tid / 16, tc = tid % 16;
    float acc[4][4] = {};
    for (int kb = 0; kb < 2; kb++) {
        const float* Asrc = kb ? x : g_aggx;
        const float* Wsrc = kb ? Wroot : Wr;
        __syncthreads();
        for (int i = tid; i < 64 * 32; i += 256) {
            int r = i >> 5, k = i & 31;
            sA[r][k] = Asrc[(size_t)(m0 + r) * 32 + k];
        }
        for (int i = tid; i < 32 * 64; i += 256) {
            int r = i >> 6, cc = i & 63;
            sW[r][cc] = Wsrc[(size_t)r * 64 + cc];
        }
        __syncthreads();
        for (int k = 0; k < 32; k++) {
            float a[4], w[4];
#pragma unroll
            for (int i = 0; i < 4; i++) a[i] = sA[tr * 4 + i][k];
#pragma unroll
            for (int j = 0; j < 4; j++) w[j] = sW[k][tc * 4 + j];
#pragma unroll
            for (int i = 0; i < 4; i++)
#pragma unroll
                for (int j = 0; j < 4; j++) acc[i][j] += a[i] * w[j];
        }
    }
#pragma unroll
    for (int i = 0; i < 4; i++)
#pragma unroll
        for (int j = 0; j < 4; j++) {
            float v = acc[i][j] + b[tc * 4 + j];
            size_t off = (size_t)(m0 + tr * 4 + i) * 64 + tc * 4 + j;
            emb[off] = v;
            g_xr[off] = fmaxf(v, 0.f);
        }
}

// ---------------- PRE: g_pre[L] = aggxr@Wr[:64] + xr@Wroot[:64] + b ---------------
// M = T*N = 240000, K = 64+64, Nout = 256 (grid.y = 4 col-tiles of 64).
__global__ __launch_bounds__(256) void k_pre(int L, const float* __restrict__ Wr,
                                             const float* __restrict__ Wroot,
                                             const float* __restrict__ b) {
    __shared__ float sA[64][33];
    __shared__ float sW[32][65];
    int m0 = blockIdx.x * 64;
    int bcol = blockIdx.y * 64;
    int tid = threadIdx.x;
    int tr = tid / 16, tc = tid % 16;
    float acc[4][4] = {};
    for (int kb = 0; kb < 4; kb++) {
        const float* Asrc = (kb < 2) ? g_aggxr : g_xr;
        const float* Wsrc = (kb < 2) ? Wr : Wroot;
        int koff = (kb & 1) * 32;
        __syncthreads();
        for (int i = tid; i < 64 * 32; i += 256) {
            int r = i >> 5, k = i & 31;
            sA[r][k] = Asrc[(size_t)(m0 + r) * 64 + koff + k];
        }
        for (int i = tid; i < 32 * 64; i += 256) {
            int r = i >> 6, cc = i & 63;
            sW[r][cc] = Wsrc[(size_t)(koff + r) * 256 + bcol + cc];
        }
        __syncthreads();
        for (int k = 0; k < 32; k++) {
            float a[4], w[4];
#pragma unroll
            for (int i = 0; i < 4; i++) a[i] = sA[tr * 4 + i][k];
#pragma unroll
            for (int j = 0; j < 4; j++) w[j] = sW[k][tc * 4 + j];
#pragma unroll
            for (int i = 0; i < 4; i++)
#pragma unroll
                for (int j = 0; j < 4; j++) acc[i][j] += a[i] * w[j];
        }
    }
    float* pre = g_pre[L];
#pragma unroll
    for (int i = 0; i < 4; i++)
#pragma unroll
        for (int j = 0; j < 4; j++)
            pre[(size_t)(m0 + tr * 4 + i) * 256 + bcol + tc * 4 + j] =
                acc[i][j] + b[bcol + tc * 4 + j];
}

// ---------------- LSTM cell: gates GEMM (K=128 over [aggh|h]) + pointwise ---------
// M = N = 20000 (tiles of 64, last tile partial). All 256 gate cols per tile so the
// i/f/g/o combine happens in registers: thread owns 4 nodes x 4 hcols x 4 gates.
__global__ __launch_bounds__(256) void k_cell(int L, int t, int parity,
                                              const float* __restrict__ Wr,
                                              const float* __restrict__ Wroot,
                                              int store) {
    __shared__ float sA[64][33];
    __shared__ float sW[32][257];
    const float* __restrict__ pre = g_pre[L] + (size_t)t * NN * 256;
    const float* __restrict__ hin = g_h[parity];
    float* __restrict__ hout = g_h[parity ^ 1];
    int m0 = blockIdx.x * 64;
    int tid = threadIdx.x;
    int tr = tid / 16, tc = tid % 16;
    float acc[4][4][4] = {};  // [node][hcol][gate]
    for (int kb = 0; kb < 4; kb++) {
        const float* Asrc = (kb < 2) ? g_aggh : hin;
        const float* Wsrc = (kb < 2) ? Wr : Wroot;
        int koff = (kb & 1) * 32;
        int wrow = 64 + koff;
        __syncthreads();
        for (int i = tid; i < 64 * 32; i += 256) {
            int r = i >> 5, k = i & 31;
            int m = m0 + r;
            sA[r][k] = (m < NN) ? Asrc[(size_t)m * 64 + koff + k] : 0.f;
        }
        for (int i = tid; i < 32 * 256; i += 256) {
            int r = i >> 8, cc = i & 255;
            sW[r][cc] = Wsrc[(size_t)(wrow + r) * 256 + cc];
        }
        __syncthreads();
        for (int k = 0; k < 32; k++) {
            float a[4];
#pragma unroll
            for (int i = 0; i < 4; i++) a[i] = sA[tr * 4 + i][k];
#pragma unroll
            for (int j = 0; j < 4; j++) {
#pragma unroll
                for (int g = 0; g < 4; g++) {
                    float w = sW[k][tc * 4 + j + g * 64];
#pragma unroll
                    for (int i = 0; i < 4; i++) acc[i][j][g] += a[i] * w;
                }
            }
        }
    }
#pragma unroll
    for (int i = 0; i < 4; i++) {
        int m = m0 + tr * 4 + i;
        if (m >= NN) continue;
#pragma unroll
        for (int j = 0; j < 4; j++) {
            int hc = tc * 4 + j;
            size_t pb = (size_t)m * 256 + hc;
            float gi = acc[i][j][0] + pre[pb];
            float gf = acc[i][j][1] + pre[pb + 64];
            float gg = acc[i][j][2] + pre[pb + 128];
            float go = acc[i][j][3] + pre[pb + 192];
            size_t hb = (size_t)m * 64 + hc;
            float cold = g_c[hb];
            float si = 1.f / (1.f + expf(-gi));
            float sf = 1.f / (1.f + expf(-gf));
            float so = 1.f / (1.f + expf(-go));
            float cn = sf * cold + si * tanhf(gg);
            float hn = so * tanhf(cn);
            g_c[hb] = cn;
            hout[hb] = hn;
            if (store >= 0) g_h2last[(size_t)store * NN * 64 + hb] = hn;
        }
    }
}

// ---------------- final projection: out = [xr, h2][-4:] @ W_out + b_out -----------
__global__ __launch_bounds__(256) void k_out(const float* __restrict__ Wout,
                                             const float* __restrict__ bout,
                                             float* __restrict__ out) {
    __shared__ float sX[32][129];  // [node][k<64: xr, k>=64: h2]
    __shared__ float sW[128][9];
    int tt = blockIdx.y;
    int n0 = blockIdx.x * 32;
    int tid = threadIdx.x;
    for (int i = tid; i < 32 * 64; i += 256) {
        int r = i >> 6, k = i & 63;
        int m = n0 + r;
        sX[r][k] = (m < NN) ? g_xr[((size_t)(TT - 4 + tt) * NN + m) * 64 + k] : 0.f;
        sX[r][64 + k] = (m < NN) ? g_h2last[((size_t)tt * NN + m) * 64 + k] : 0.f;
    }
    for (int i = tid; i < 128 * 8; i += 256) sW[i >> 3][i & 7] = Wout[i];
    __syncthreads();
    int node = tid >> 3, o = tid & 7;
    float acc = bout[o];
    for (int k = 0; k < 128; k++) acc += sX[node][k] * sW[k][o];
    int m = n0 + node;
    if (m < NN) out[((size_t)tt * NN + m) * 8 + o] = acc;
}

// ---------------- misc ------------------------------------------------------------
__global__ void k_zero_state() {
    int i = blockIdx.x * blockDim.x + threadIdx.x;
    if (i < NN * HH) { g_h[0][i] = 0.f; g_c[i] = 0.f; }
}

__global__ void k_copy_c2(float* __restrict__ dst) {
    int i = blockIdx.x * blockDim.x + threadIdx.x;
    if (i < NN * HH) dst[i] = g_c[i];
}

// ---------------- launch ----------------------------------------------------------
extern "C" void kernel_launch(void* const* d_in, const int* in_sizes, int n_in,
                              void* d_out, int out_size) {
    const float* x      = (const float*)d_in[0];
    const int*   ei     = (const int*)d_in[1];
    const float* ew     = (const float*)d_in[2];
    const float* sWr    = (const float*)d_in[3];
    const float* sWroot = (const float*)d_in[4];
    const float* sb     = (const float*)d_in[5];
    const float* Wr1    = (const float*)d_in[6];
    const float* Wroot1 = (const float*)d_in[7];
    const float* b1     = (const float*)d_in[8];
    const float* Wr2    = (const float*)d_in[9];
    const float* Wroot2 = (const float*)d_in[10];
    const float* b2     = (const float*)d_in[11];
    const float* Wout   = (const float*)d_in[12];
    const float* bout   = (const float*)d_in[13];
    float* out = (float*)d_out;
    const int* src = ei;
    const int* dst = ei + EE;

    // CSR build (per launch — must be deterministic & stateless)
    k_zero_cursor<<<(NN + 255) / 256, 256>>>();
    k_deg<<<(EE + 255) / 256, 256>>>(dst);
    k_scan<<<1, 1024>>>();
    k_fill<<<(EE + 255) / 256, 256>>>(src, dst, ew);

    // SAGE embedding
    dim3 aggGridT(2500, TT);
    k_agg<32><<<aggGridT, 256>>>(0, 0, x);
    k_sage<<<TT * NN / 64, 256>>>(x, sWr, sWroot, sb, out + EMB_OFF);

    // Precompute the x-dependent half of every LSTM step's gates (parallel over T)
    k_agg<64><<<aggGridT, 256>>>(1, 0, nullptr);
    k_pre<<<dim3(TT * NN / 64, 4), 256>>>(0, Wr1, Wroot1, b1);
    k_pre<<<dim3(TT * NN / 64, 4), 256>>>(1, Wr2, Wroot2, b2);

    // Sequential LSTM steps (LSTM2 continues from LSTM1's final state)
    k_zero_state<<<(NN * HH + 255) / 256, 256>>>();
    int par = 0;
    for (int L = 0; L < 2; L++) {
        const float* Wr = L ? Wr2 : Wr1;
        const float* Wroot = L ? Wroot2 : Wroot1;
        for (int t = 0; t < TT; t++) {
            k_agg<64><<<dim3(2500, 1), 256>>>(2, par, nullptr);
            int store = (L == 1 && t >= TT - 4) ? (t - (TT - 4)) : -1;
            k_cell<<<(NN + 63) / 64, 256>>>(L, t, par, Wr, Wroot, store);
            par ^= 1;
        }
    }

    k_out<<<dim3(NN / 32, 4), 256>>>(Wout, bout, out + OUT_OFF);
    k_copy_c2<<<(NN * HH + 255) / 256, 256>>>(out + C2_OFF);
}

// round 2
// speedup vs baseline: 1.2319x; 1.2319x over previous
#include <cuda_runtime.h>
#include <math.h>

#define TT 12
#define NN 20000
#define EE 400000
#define FF 32
#define HH 64
#define OO 8

// Output layout (flattened tuple): out[4,N,8] | c2[N,64] | emb[T,N,64]
#define OUT_OFF 0
#define C2_OFF  (4*NN*OO)                 // 640000
#define EMB_OFF (C2_OFF + NN*HH)          // 1920000

// ---------------- scratch (static device globals; allocation-free at runtime) ----
__device__ int   g_rowptr[NN + 1];
__device__ int   g_cursor[NN];
__device__ int   g_csr_src[EE];
__device__ float g_csr_w[EE];
__device__ float g_xr[TT * NN * HH];          // relu(emb)
__device__ float g_aggx[TT * NN * FF];        // wmean(x) per t
__device__ float g_aggxr[TT * NN * HH];       // wmean(xr) per t
__device__ float g_pre[2][TT * NN * 4 * HH];  // precomputed gate contributions per LSTM
__device__ float g_h[2][NN * HH];             // ping-pong hidden state
__device__ float g_c[NN * HH];
__device__ float g_aggh[NN * HH];
__device__ float g_h2last[4 * NN * HH];       // h2 for last 4 steps

// ---------------- packed f32x2 helpers (FFMA2 — ptxas never auto-emits) -----------
__device__ __forceinline__ unsigned long long pk2(float lo, float hi) {
    unsigned long long r;
    asm("mov.b64 %0, {%1,%2};" : "=l"(r) : "f"(lo), "f"(hi));
    return r;
}
__device__ __forceinline__ void upk2(unsigned long long v, float& lo, float& hi) {
    asm("mov.b64 {%0,%1}, %2;" : "=f"(lo), "=f"(hi) : "l"(v));
}
__device__ __forceinline__ unsigned long long ffma2(unsigned long long a,
                                                    unsigned long long b,
                                                    unsigned long long c) {
    unsigned long long d;
    asm("fma.rn.f32x2 %0, %1, %2, %3;" : "=l"(d) : "l"(a), "l"(b), "l"(c));
    return d;
}

// ---------------- CSR construction ------------------------------------------------
__global__ void k_zero_cursor() {
    int i = blockIdx.x * blockDim.x + threadIdx.x;
    if (i < NN) g_cursor[i] = 0;
}

__global__ void k_deg(const int* __restrict__ dst) {
    int e = blockIdx.x * blockDim.x + threadIdx.x;
    if (e < EE) atomicAdd(&g_cursor[dst[e]], 1);
}

// Single-block exclusive scan of g_cursor (N=20000) -> g_rowptr, and reset cursor.
__global__ void k_scan() {
    __shared__ int wsum[32];
    const int CH = 20;  // 1024 * 20 = 20480 >= 20000
    int tid = threadIdx.x;
    int base = tid * CH;
    int loc[CH];
    int s = 0;
#pragma unroll
    for (int i = 0; i < CH; i++) {
        int idx = base + i;
        int v = (idx < NN) ? g_cursor[idx] : 0;
        loc[i] = s;
        s += v;
    }
    int lane = tid & 31, w = tid >> 5;
    int inc = s;
#pragma unroll
    for (int o = 1; o < 32; o <<= 1) {
        int t = __shfl_up_sync(0xffffffffu, inc, o);
        if (lane >= o) inc += t;
    }
    if (lane == 31) wsum[w] = inc;
    __syncthreads();
    if (w == 0) {
        int v = wsum[lane];
#pragma unroll
        for (int o = 1; o < 32; o <<= 1) {
            int t = __shfl_up_sync(0xffffffffu, v, o);
            if (lane >= o) v += t;
        }
        wsum[lane] = v;
    }
    __syncthreads();
    int excl = inc - s + (w > 0 ? wsum[w - 1] : 0);
#pragma unroll
    for (int i = 0; i < CH; i++) {
        int idx = base + i;
        if (idx < NN) {
            int p = excl + loc[i];
            g_rowptr[idx] = p;
            g_cursor[idx] = p;
        }
    }
    if (tid == 0) g_rowptr[NN] = EE;
}

__global__ void k_fill(const int* __restrict__ src, const int* __restrict__ dst,
                       const float* __restrict__ ew) {
    int e = blockIdx.x * blockDim.x + threadIdx.x;
    if (e < EE) {
        int d = dst[e];
        int pos = atomicAdd(&g_cursor[d], 1);
        g_csr_src[pos] = src[e];
        g_csr_w[pos] = ew[e];
    }
}

// ---------------- weighted-mean aggregation (CSR, warp per node) ------------------
// mode 0: in = xin + t*N*FD  -> g_aggx   (FD=32)
// mode 1: in = g_xr + t*N*FD -> g_aggxr  (FD=64)
// mode 2: in = g_h[parity]   -> g_aggh   (FD=64, single t)
template <int FD>
__global__ void k_agg(int mode, int parity, const float* __restrict__ xin) {
    int gw = (blockIdx.x * blockDim.x + threadIdx.x) >> 5;
    int lane = threadIdx.x & 31;
    if (gw >= NN) return;
    size_t toff = (size_t)blockIdx.y * NN * FD;
    const float* __restrict__ in;
    float* __restrict__ out;
    if (mode == 0) { in = xin + toff;   out = g_aggx + toff; }
    else if (mode == 1) { in = g_xr + toff; out = g_aggxr + toff; }
    else { in = g_h[parity]; out = g_aggh; }

    int e0 = g_rowptr[gw], e1 = g_rowptr[gw + 1];
    float acc[FD / 32];
#pragma unroll
    for (int i = 0; i < FD / 32; i++) acc[i] = 0.f;
    for (int e = e0; e < e1; e++) {
        int s = __ldg(&g_csr_src[e]);
        float w = __ldg(&g_csr_w[e]);
#pragma unroll
        for (int i = 0; i < FD / 32; i++)
            acc[i] += w * __ldg(&in[(size_t)s * FD + lane + 32 * i]);
    }
    float inv = 1.f / (float)max(e1 - e0, 1);
#pragma unroll
    for (int i = 0; i < FD / 32; i++)
        out[(size_t)gw * FD + lane + 32 * i] = acc[i] * inv;
}

// ---------------- SAGE: emb = aggx@Wr + x@Wroot + b ; xr = relu(emb) --------------
__global__ __launch_bounds__(256) void k_sage(const float* __restrict__ x,
                                              const float* __restrict__ Wr,
                                              const float* __restrict__ Wroot,
                                              const float* __restrict__ b,
                                              float* __restrict__ emb) {
    __shared__ float sA[64][33];
    __shared__ float sW[32][65];
    int m0 = blockIdx.x * 64;
    int tid = threadIdx.x;
    int tr = tid / 16, tc = tid % 16;
    float acc[4][4] = {};
    for (int kb = 0; kb < 2; kb++) {
        const float* Asrc = kb ? x : g_aggx;
        const float* Wsrc = kb ? Wroot : Wr;
        __syncthreads();
        for (int i = tid; i < 64 * 32; i += 256) {
            int r = i >> 5, k = i & 31;
            sA[r][k] = Asrc[(size_t)(m0 + r) * 32 + k];
        }
        for (int i = tid; i < 32 * 64; i += 256) {
            int r = i >> 6, cc = i & 63;
            sW[r][cc] = Wsrc[(size_t)r * 64 + cc];
        }
        __syncthreads();
        for (int k = 0; k < 32; k++) {
            float a[4], w[4];
#pragma unroll
            for (int i = 0; i < 4; i++) a[i] = sA[tr * 4 + i][k];
#pragma unroll
            for (int j = 0; j < 4; j++) w[j] = sW[k][tc * 4 + j];
#pragma unroll
            for (int i = 0; i < 4; i++)
#pragma unroll
                for (int j = 0; j < 4; j++) acc[i][j] += a[i] * w[j];
        }
    }
#pragma unroll
    for (int i = 0; i < 4; i++)
#pragma unroll
        for (int j = 0; j < 4; j++) {
            float v = acc[i][j] + b[tc * 4 + j];
            size_t off = (size_t)(m0 + tr * 4 + i) * 64 + tc * 4 + j;
            emb[off] = v;
            g_xr[off] = fmaxf(v, 0.f);
        }
}

// ---------------- PRE: g_pre[L] = [aggxr|xr] @ Wrows[0:64] + b  (f32x2 core) ------
// M = T*N = 240000, K = 128 (aggxr 64 | xr 64), Nout = 256. Tile 64x256/block.
// Thread tile: 4 rows x 8 cols as 4x2x(gate 4) f32x2 pairs.
__global__ __launch_bounds__(256, 2) void k_pre(int L, const float* __restrict__ Wr,
                                                const float* __restrict__ Wroot,
                                                const float* __restrict__ b) {
    __shared__ float sA[64][33];
    __shared__ float sW[32][258];   // even pad -> LDS.64-aligned pairs
    int m0 = blockIdx.x * 64;
    int tid = threadIdx.x;
    int tr = tid / 16, tc = tid % 16;
    unsigned long long acc[4][2][4];
#pragma unroll
    for (int i = 0; i < 4; i++)
#pragma unroll
        for (int j2 = 0; j2 < 2; j2++)
#pragma unroll
            for (int g = 0; g < 4; g++) acc[i][j2][g] = 0ull;

    for (int kb = 0; kb < 4; kb++) {
        const float* Asrc = (kb < 2) ? g_aggxr : g_xr;
        const float* Wsrc = (kb < 2) ? Wr : Wroot;
        int koff = (kb & 1) * 32;
        __syncthreads();
        for (int i = tid; i < 64 * 32; i += 256) {
            int r = i >> 5, k = i & 31;
            sA[r][k] = Asrc[(size_t)(m0 + r) * 64 + koff + k];
        }
        for (int i = tid; i < 32 * 256; i += 256) {
            int r = i >> 8, cc = i & 255;
            sW[r][cc] = Wsrc[(size_t)(koff + r) * 256 + cc];
        }
        __syncthreads();
#pragma unroll
        for (int k = 0; k < 32; k++) {
            unsigned long long a2[4];
#pragma unroll
            for (int i = 0; i < 4; i++) {
                float av = sA[tr * 4 + i][k];
                a2[i] = pk2(av, av);
            }
#pragma unroll
            for (int g = 0; g < 4; g++)
#pragma unroll
                for (int j2 = 0; j2 < 2; j2++) {
                    unsigned long long w2 =
                        *(const unsigned long long*)&sW[k][tc * 4 + j2 * 2 + g * 64];
#pragma unroll
                    for (int i = 0; i < 4; i++)
                        acc[i][j2][g] = ffma2(a2[i], w2, acc[i][j2][g]);
                }
        }
    }
    float* pre = g_pre[L];
#pragma unroll
    for (int i = 0; i < 4; i++) {
        size_t mrow = (size_t)(m0 + tr * 4 + i) * 256;
#pragma unroll
        for (int j2 = 0; j2 < 2; j2++)
#pragma unroll
            for (int g = 0; g < 4; g++) {
                float v0, v1;
                upk2(acc[i][j2][g], v0, v1);
                int c0 = tc * 4 + j2 * 2 + g * 64;
                pre[mrow + c0]     = v0 + b[c0];
                pre[mrow + c0 + 1] = v1 + b[c0 + 1];
            }
    }
}

// ---------------- LSTM cell: gates GEMM (K=128 over [aggh|h]) + pointwise ---------
// f32x2 core, same tiling as k_pre. Gate combine + activations in registers.
__global__ __launch_bounds__(256, 2) void k_cell(int L, int t, int parity,
                                                 const float* __restrict__ Wr,
                                                 const float* __restrict__ Wroot,
                                                 int store) {
    __shared__ float sA[64][33];
    __shared__ float sW[32][258];
    const float* __restrict__ pre = g_pre[L] + (size_t)t * NN * 256;
    const float* __restrict__ hin = g_h[parity];
    float* __restrict__ hout = g_h[parity ^ 1];
    int m0 = blockIdx.x * 64;
    int tid = threadIdx.x;
    int tr = tid / 16, tc = tid % 16;
    unsigned long long acc[4][2][4];
#pragma unroll
    for (int i = 0; i < 4; i++)
#pragma unroll
        for (int j2 = 0; j2 < 2; j2++)
#pragma unroll
            for (int g = 0; g < 4; g++) acc[i][j2][g] = 0ull;

    for (int kb = 0; kb < 4; kb++) {
        const float* Asrc = (kb < 2) ? g_aggh : hin;
        const float* Wsrc = (kb < 2) ? Wr : Wroot;
        int koff = (kb & 1) * 32;
        int wrow = 64 + koff;                 // h-part rows of the (128,256) weights
        __syncthreads();
        for (int i = tid; i < 64 * 32; i += 256) {
            int r = i >> 5, k = i & 31;
            int m = m0 + r;
            sA[r][k] = (m < NN) ? Asrc[(size_t)m * 64 + koff + k] : 0.f;
        }
        for (int i = tid; i < 32 * 256; i += 256) {
            int r = i >> 8, cc = i & 255;
            sW[r][cc] = Wsrc[(size_t)(wrow + r) * 256 + cc];
        }
        __syncthreads();
#pragma unroll
        for (int k = 0; k < 32; k++) {
            unsigned long long a2[4];
#pragma unroll
            for (int i = 0; i < 4; i++) {
                float av = sA[tr * 4 + i][k];
                a2[i] = pk2(av, av);
            }
#pragma unroll
            for (int g = 0; g < 4; g++)
#pragma unroll
                for (int j2 = 0; j2 < 2; j2++) {
                    unsigned long long w2 =
                        *(const unsigned long long*)&sW[k][tc * 4 + j2 * 2 + g * 64];
#pragma unroll
                    for (int i = 0; i < 4; i++)
                        acc[i][j2][g] = ffma2(a2[i], w2, acc[i][j2][g]);
                }
        }
    }
#pragma unroll
    for (int i = 0; i < 4; i++) {
        int m = m0 + tr * 4 + i;
        if (m >= NN) continue;
#pragma unroll
        for (int j2 = 0; j2 < 2; j2++) {
            float v[4][2];
#pragma unroll
            for (int g = 0; g < 4; g++) upk2(acc[i][j2][g], v[g][0], v[g][1]);
#pragma unroll
            for (int l = 0; l < 2; l++) {
                int hc = tc * 4 + j2 * 2 + l;
                size_t pb = (size_t)m * 256 + hc;
                float gi = v[0][l] + pre[pb];
                float gf = v[1][l] + pre[pb + 64];
                float gg = v[2][l] + pre[pb + 128];
                float go = v[3][l] + pre[pb + 192];
                size_t hb = (size_t)m * 64 + hc;
                float cold = g_c[hb];
                float si = __fdividef(1.f, 1.f + __expf(-gi));
                float sf = __fdividef(1.f, 1.f + __expf(-gf));
                float so = __fdividef(1.f, 1.f + __expf(-go));
                float cn = sf * cold + si * tanhf(gg);
                float hn = so * tanhf(cn);
                g_c[hb] = cn;
                hout[hb] = hn;
                if (store >= 0) g_h2last[(size_t)store * NN * 64 + hb] = hn;
            }
        }
    }
}

// ---------------- final projection: out = [xr, h2][-4:] @ W_out + b_out -----------
__global__ __launch_bounds__(256) void k_out(const float* __restrict__ Wout,
                                             const float* __restrict__ bout,
                                             float* __restrict__ out) {
    __shared__ float sX[32][129];
    __shared__ float sW[128][9];
    int tt = blockIdx.y;
    int n0 = blockIdx.x * 32;
    int tid = threadIdx.x;
    for (int i = tid; i < 32 * 64; i += 256) {
        int r = i >> 6, k = i & 63;
        int m = n0 + r;
        sX[r][k] = (m < NN) ? g_xr[((size_t)(TT - 4 + tt) * NN + m) * 64 + k] : 0.f;
        sX[r][64 + k] = (m < NN) ? g_h2last[((size_t)tt * NN + m) * 64 + k] : 0.f;
    }
    for (int i = tid; i < 128 * 8; i += 256) sW[i >> 3][i & 7] = Wout[i];
    __syncthreads();
    int node = tid >> 3, o = tid & 7;
    float acc = bout[o];
    for (int k = 0; k < 128; k++) acc += sX[node][k] * sW[k][o];
    int m = n0 + node;
    if (m < NN) out[((size_t)tt * NN + m) * 8 + o] = acc;
}

// ---------------- misc ------------------------------------------------------------
__global__ void k_zero_state() {
    int i = blockIdx.x * blockDim.x + threadIdx.x;
    if (i < NN * HH) { g_h[0][i] = 0.f; g_c[i] = 0.f; }
}

__global__ void k_copy_c2(float* __restrict__ dst) {
    int i = blockIdx.x * blockDim.x + threadIdx.x;
    if (i < NN * HH) dst[i] = g_c[i];
}

// ---------------- launch ----------------------------------------------------------
extern "C" void kernel_launch(void* const* d_in, const int* in_sizes, int n_in,
                              void* d_out, int out_size) {
    const float* x      = (const float*)d_in[0];
    const int*   ei     = (const int*)d_in[1];
    const float* ew     = (const float*)d_in[2];
    const float* sWr    = (const float*)d_in[3];
    const float* sWroot = (const float*)d_in[4];
    const float* sb     = (const float*)d_in[5];
    const float* Wr1    = (const float*)d_in[6];
    const float* Wroot1 = (const float*)d_in[7];
    const float* b1     = (const float*)d_in[8];
    const float* Wr2    = (const float*)d_in[9];
    const float* Wroot2 = (const float*)d_in[10];
    const float* b2     = (const float*)d_in[11];
    const float* Wout   = (const float*)d_in[12];
    const float* bout   = (const float*)d_in[13];
    float* out = (float*)d_out;
    const int* src = ei;
    const int* dst = ei + EE;

    // CSR build (per launch — deterministic & stateless)
    k_zero_cursor<<<(NN + 255) / 256, 256>>>();
    k_deg<<<(EE + 255) / 256, 256>>>(dst);
    k_scan<<<1, 1024>>>();
    k_fill<<<(EE + 255) / 256, 256>>>(src, dst, ew);

    // SAGE embedding
    dim3 aggGridT(2500, TT);
    k_agg<32><<<aggGridT, 256>>>(0, 0, x);
    k_sage<<<TT * NN / 64, 256>>>(x, sWr, sWroot, sb, out + EMB_OFF);

    // Precompute the x-dependent half of every LSTM step's gates (parallel over T)
    k_agg<64><<<aggGridT, 256>>>(1, 0, nullptr);
    k_pre<<<TT * NN / 64, 256>>>(0, Wr1, Wroot1, b1);
    k_pre<<<TT * NN / 64, 256>>>(1, Wr2, Wroot2, b2);

    // Sequential LSTM steps (LSTM2 continues from LSTM1's final state)
    k_zero_state<<<(NN * HH + 255) / 256, 256>>>();
    int par = 0;
    for (int L = 0; L < 2; L++) {
        const float* Wr = L ? Wr2 : Wr1;
        const float* Wroot = L ? Wroot2 : Wroot1;
        for (int t = 0; t < TT; t++) {
            k_agg<64><<<dim3(2500, 1), 256>>>(2, par, nullptr);
            int store = (L == 1 && t >= TT - 4) ? (t - (TT - 4)) : -1;
            k_cell<<<(NN + 63) / 64, 256>>>(L, t, par, Wr, Wroot, store);
            par ^= 1;
        }
    }

    k_out<<<dim3(NN / 32, 4), 256>>>(Wout, bout, out + OUT_OFF);
    k_copy_c2<<<(NN * HH + 255) / 256, 256>>>(out + C2_OFF);
}

// round 3
// speedup vs baseline: 1.7959x; 1.4579x over previous
#include <cuda_runtime.h>
#include <math.h>

#define TT 12
#define NN 20000
#define EE 400000
#define FF 32
#define HH 64
#define OO 8

// Output layout (flattened tuple): out[4,N,8] | c2[N,64] | emb[T,N,64]
#define OUT_OFF 0
#define C2_OFF  (4*NN*OO)                 // 640000
#define EMB_OFF (C2_OFF + NN*HH)          // 1920000

// ---------------- scratch (static device globals; allocation-free at runtime) ----
__device__ int   g_rowptr[NN + 1];
__device__ int   g_cursor[NN];
__device__ int   g_csr_src[EE];
__device__ float g_csr_w[EE];
__device__ float g_xr[TT * NN * HH];          // relu(emb)
__device__ float g_aggx[TT * NN * FF];        // wmean(x) per t
__device__ float g_aggxr[TT * NN * HH];       // wmean(xr) per t
__device__ float g_pre[2][TT * NN * 4 * HH];  // precomputed gate contributions per LSTM
__device__ float g_h[2][NN * HH];             // ping-pong hidden state
__device__ float g_c[NN * HH];
__device__ float g_aggh[NN * HH];
__device__ float g_h2last[4 * NN * HH];       // h2 for last 4 steps

// ---------------- mma.sync tf32 helpers -------------------------------------------
__device__ __forceinline__ unsigned f2tf32(float f) {
    unsigned r;
    asm("cvt.rna.tf32.f32 %0, %1;" : "=r"(r) : "f"(f));
    return r;
}
__device__ __forceinline__ void mma8(float* c, const uint4 a, unsigned b0, unsigned b1) {
    asm volatile(
        "mma.sync.aligned.m16n8k8.row.col.f32.tf32.tf32.f32 "
        "{%0,%1,%2,%3},{%4,%5,%6,%7},{%8,%9},{%0,%1,%2,%3};"
        : "+f"(c[0]), "+f"(c[1]), "+f"(c[2]), "+f"(c[3])
        : "r"(a.x), "r"(a.y), "r"(a.z), "r"(a.w), "r"(b0), "r"(b1));
}

// ---------------- CSR construction ------------------------------------------------
__global__ void k_zero_cursor() {
    int i = blockIdx.x * blockDim.x + threadIdx.x;
    if (i < NN) g_cursor[i] = 0;
}

__global__ void k_deg(const int* __restrict__ dst) {
    int e = blockIdx.x * blockDim.x + threadIdx.x;
    if (e < EE) atomicAdd(&g_cursor[dst[e]], 1);
}

__global__ void k_scan() {
    __shared__ int wsum[32];
    const int CH = 20;
    int tid = threadIdx.x;
    int base = tid * CH;
    int loc[CH];
    int s = 0;
#pragma unroll
    for (int i = 0; i < CH; i++) {
        int idx = base + i;
        int v = (idx < NN) ? g_cursor[idx] : 0;
        loc[i] = s;
        s += v;
    }
    int lane = tid & 31, w = tid >> 5;
    int inc = s;
#pragma unroll
    for (int o = 1; o < 32; o <<= 1) {
        int t = __shfl_up_sync(0xffffffffu, inc, o);
        if (lane >= o) inc += t;
    }
    if (lane == 31) wsum[w] = inc;
    __syncthreads();
    if (w == 0) {
        int v = wsum[lane];
#pragma unroll
        for (int o = 1; o < 32; o <<= 1) {
            int t = __shfl_up_sync(0xffffffffu, v, o);
            if (lane >= o) v += t;
        }
        wsum[lane] = v;
    }
    __syncthreads();
    int excl = inc - s + (w > 0 ? wsum[w - 1] : 0);
#pragma unroll
    for (int i = 0; i < CH; i++) {
        int idx = base + i;
        if (idx < NN) {
            int p = excl + loc[i];
            g_rowptr[idx] = p;
            g_cursor[idx] = p;
        }
    }
    if (tid == 0) g_rowptr[NN] = EE;
}

__global__ void k_fill(const int* __restrict__ src, const int* __restrict__ dst,
                       const float* __restrict__ ew) {
    int e = blockIdx.x * blockDim.x + threadIdx.x;
    if (e < EE) {
        int d = dst[e];
        int pos = atomicAdd(&g_cursor[d], 1);
        g_csr_src[pos] = src[e];
        g_csr_w[pos] = ew[e];
    }
}

// ---------------- weighted-mean aggregation (CSR, warp per node) ------------------
template <int FD>
__global__ void k_agg(int mode, int parity, const float* __restrict__ xin) {
    int gw = (blockIdx.x * blockDim.x + threadIdx.x) >> 5;
    int lane = threadIdx.x & 31;
    if (gw >= NN) return;
    size_t toff = (size_t)blockIdx.y * NN * FD;
    const float* __restrict__ in;
    float* __restrict__ out;
    if (mode == 0) { in = xin + toff;   out = g_aggx + toff; }
    else if (mode == 1) { in = g_xr + toff; out = g_aggxr + toff; }
    else { in = g_h[parity]; out = g_aggh; }

    int e0 = g_rowptr[gw], e1 = g_rowptr[gw + 1];
    float acc[FD / 32];
#pragma unroll
    for (int i = 0; i < FD / 32; i++) acc[i] = 0.f;
    for (int e = e0; e < e1; e++) {
        int s = __ldg(&g_csr_src[e]);
        float w = __ldg(&g_csr_w[e]);
#pragma unroll
        for (int i = 0; i < FD / 32; i++)
            acc[i] += w * __ldg(&in[(size_t)s * FD + lane + 32 * i]);
    }
    float inv = 1.f / (float)max(e1 - e0, 1);
#pragma unroll
    for (int i = 0; i < FD / 32; i++)
        out[(size_t)gw * FD + lane + 32 * i] = acc[i] * inv;
}

// ---------------- SAGE: emb = aggx@Wr + x@Wroot + b ; xr = relu(emb)  (fp32) ------
__global__ __launch_bounds__(256) void k_sage(const float* __restrict__ x,
                                              const float* __restrict__ Wr,
                                              const float* __restrict__ Wroot,
                                              const float* __restrict__ b,
                                              float* __restrict__ emb) {
    __shared__ float sA[64][33];
    __shared__ float sW[32][65];
    int m0 = blockIdx.x * 64;
    int tid = threadIdx.x;
    int tr = tid / 16, tc = tid % 16;
    float acc[4][4] = {};
    for (int kb = 0; kb < 2; kb++) {
        const float* Asrc = kb ? x : g_aggx;
        const float* Wsrc = kb ? Wroot : Wr;
        __syncthreads();
        for (int i = tid; i < 64 * 32; i += 256) {
            int r = i >> 5, k = i & 31;
            sA[r][k] = Asrc[(size_t)(m0 + r) * 32 + k];
        }
        for (int i = tid; i < 32 * 64; i += 256) {
            int r = i >> 6, cc = i & 63;
            sW[r][cc] = Wsrc[(size_t)r * 64 + cc];
        }
        __syncthreads();
        for (int k = 0; k < 32; k++) {
            float a[4], w[4];
#pragma unroll
            for (int i = 0; i < 4; i++) a[i] = sA[tr * 4 + i][k];
#pragma unroll
            for (int j = 0; j < 4; j++) w[j] = sW[k][tc * 4 + j];
#pragma unroll
            for (int i = 0; i < 4; i++)
#pragma unroll
                for (int j = 0; j < 4; j++) acc[i][j] += a[i] * w[j];
        }
    }
#pragma unroll
    for (int i = 0; i < 4; i++)
#pragma unroll
        for (int j = 0; j < 4; j++) {
            float v = acc[i][j] + b[tc * 4 + j];
            size_t off = (size_t)(m0 + tr * 4 + i) * 64 + tc * 4 + j;
            emb[off] = v;
            g_xr[off] = fmaxf(v, 0.f);
        }
}

// ---------------- PRE (tf32 mma): g_pre[L] = [aggxr|xr] @ W[0:64 rows] + b --------
// Block: 128 rows x 256 cols, 512 threads (16 warps). Warp: 32 rows x 32 cols
// arranged as 2 m-frags x (4 gates x 2 col-halves) n-frags.
__global__ __launch_bounds__(512, 1) void k_pre(int L, const float* __restrict__ Wr,
                                                const float* __restrict__ Wroot,
                                                const float* __restrict__ bias) {
    __shared__ unsigned sAf[8 * 4 * 32 * 4];   // [mf 8][kk 4][lane 32][4]
    __shared__ unsigned sWf[4 * 32 * 32 * 2];  // [kk 4][n8 32][lane 32][2]
    int m0 = blockIdx.x * 128;
    int tid = threadIdx.x;
    int warp = tid >> 5, lane = tid & 31;
    int wm = warp >> 2, wn = warp & 3;
    int gid = lane >> 2, tig = lane & 3;
    float acc[2][4][2][4];
#pragma unroll
    for (int mf = 0; mf < 2; mf++)
#pragma unroll
        for (int g = 0; g < 4; g++)
#pragma unroll
            for (int hh = 0; hh < 2; hh++)
#pragma unroll
                for (int q = 0; q < 4; q++) acc[mf][g][hh][q] = 0.f;

    for (int kb = 0; kb < 4; kb++) {
        const float* Asrc = (kb < 2) ? g_aggxr : g_xr;
        const float* Wsrc = (kb < 2) ? Wr : Wroot;
        int koff = (kb & 1) * 32;
        __syncthreads();
        // stage A (128x32) fragment-major as tf32
        for (int i = tid; i < 128 * 32; i += 512) {
            int r = i >> 5, c = i & 31;
            float v = Asrc[(size_t)(m0 + r) * 64 + koff + c];
            int slot = ((((r >> 4) * 4 + (c >> 3)) * 32 + ((r & 7) * 4 + (c & 3))) << 2)
                       + (((c >> 2) & 1) * 2 + ((r >> 3) & 1));
            sAf[slot] = f2tf32(v);
        }
        // stage W (32x256) fragment-major as tf32
        for (int i = tid; i < 32 * 256; i += 512) {
            int k = i >> 8, n = i & 255;
            float v = Wsrc[(size_t)(koff + k) * 256 + n];
            int slot = ((((k >> 3) * 32 + (n >> 3)) * 32 + ((n & 7) * 4 + (k & 3))) << 1)
                       + ((k >> 2) & 1);
            sWf[slot] = f2tf32(v);
        }
        __syncthreads();
#pragma unroll
        for (int kk = 0; kk < 4; kk++) {
            uint4 a[2];
#pragma unroll
            for (int mf = 0; mf < 2; mf++)
                a[mf] = ((const uint4*)sAf)[((wm * 2 + mf) * 4 + kk) * 32 + lane];
#pragma unroll
            for (int g = 0; g < 4; g++)
#pragma unroll
                for (int hh = 0; hh < 2; hh++) {
                    int n8 = g * 8 + wn * 2 + hh;
                    uint2 b = ((const uint2*)sWf)[(kk * 32 + n8) * 32 + lane];
#pragma unroll
                    for (int mf = 0; mf < 2; mf++)
                        mma8(acc[mf][g][hh], a[mf], b.x, b.y);
                }
        }
    }
    float* pre = g_pre[L];
#pragma unroll
    for (int mf = 0; mf < 2; mf++)
#pragma unroll
        for (int rr = 0; rr < 2; rr++) {
            int m = m0 + wm * 32 + mf * 16 + gid + rr * 8;
#pragma unroll
            for (int g = 0; g < 4; g++)
#pragma unroll
                for (int hh = 0; hh < 2; hh++) {
                    int n0 = g * 64 + wn * 16 + hh * 8 + tig * 2;
                    float2 bv = *(const float2*)&bias[n0];
                    float2 v;
                    v.x = acc[mf][g][hh][rr * 2 + 0] + bv.x;
                    v.y = acc[mf][g][hh][rr * 2 + 1] + bv.y;
                    *(float2*)&pre[(size_t)m * 256 + n0] = v;
                }
        }
}

// ---------------- LSTM cell (tf32 mma): gates over [aggh|h], fused pointwise ------
// Block: 64 rows x 256 cols, 256 threads (8 warps). Warp: 32 rows x 32 cols.
__global__ __launch_bounds__(256, 2) void k_cell(int L, int t, int parity,
                                                 const float* __restrict__ Wr,
                                                 const float* __restrict__ Wroot,
                                                 int store) {
    __shared__ unsigned sAf[4 * 4 * 32 * 4];   // [mf 4][kk 4][lane 32][4]
    __shared__ unsigned sWf[4 * 32 * 32 * 2];  // [kk 4][n8 32][lane 32][2]
    const float* __restrict__ pre = g_pre[L] + (size_t)t * NN * 256;
    const float* __restrict__ hin = g_h[parity];
    float* __restrict__ hout = g_h[parity ^ 1];
    int m0 = blockIdx.x * 64;
    int tid = threadIdx.x;
    int warp = tid >> 5, lane = tid & 31;
    int wm = warp >> 2, wn = warp & 3;
    int gid = lane >> 2, tig = lane & 3;
    float acc[2][4][2][4];
#pragma unroll
    for (int mf = 0; mf < 2; mf++)
#pragma unroll
        for (int g = 0; g < 4; g++)
#pragma unroll
            for (int hh = 0; hh < 2; hh++)
#pragma unroll
                for (int q = 0; q < 4; q++) acc[mf][g][hh][q] = 0.f;

    for (int kb = 0; kb < 4; kb++) {
        const float* Asrc = (kb < 2) ? g_aggh : hin;
        const float* Wsrc = (kb < 2) ? Wr : Wroot;
        int koff = (kb & 1) * 32;
        int wrow = 64 + koff;
        __syncthreads();
        for (int i = tid; i < 64 * 32; i += 256) {
            int r = i >> 5, c = i & 31;
            int m = m0 + r;
            float v = (m < NN) ? Asrc[(size_t)m * 64 + koff + c] : 0.f;
            int slot = ((((r >> 4) * 4 + (c >> 3)) * 32 + ((r & 7) * 4 + (c & 3))) << 2)
                       + (((c >> 2) & 1) * 2 + ((r >> 3) & 1));
            sAf[slot] = f2tf32(v);
        }
        for (int i = tid; i < 32 * 256; i += 256) {
            int k = i >> 8, n = i & 255;
            float v = Wsrc[(size_t)(wrow + k) * 256 + n];
            int slot = ((((k >> 3) * 32 + (n >> 3)) * 32 + ((n & 7) * 4 + (k & 3))) << 1)
                       + ((k >> 2) & 1);
            sWf[slot] = f2tf32(v);
        }
        __syncthreads();
#pragma unroll
        for (int kk = 0; kk < 4; kk++) {
            uint4 a[2];
#pragma unroll
            for (int mf = 0; mf < 2; mf++)
                a[mf] = ((const uint4*)sAf)[((wm * 2 + mf) * 4 + kk) * 32 + lane];
#pragma unroll
            for (int g = 0; g < 4; g++)
#pragma unroll
                for (int hh = 0; hh < 2; hh++) {
                    int n8 = g * 8 + wn * 2 + hh;
                    uint2 b = ((const uint2*)sWf)[(kk * 32 + n8) * 32 + lane];
#pragma unroll
                    for (int mf = 0; mf < 2; mf++)
                        mma8(acc[mf][g][hh], a[mf], b.x, b.y);
                }
        }
    }
#pragma unroll
    for (int mf = 0; mf < 2; mf++)
#pragma unroll
        for (int rr = 0; rr < 2; rr++) {
            int m = m0 + wm * 32 + mf * 16 + gid + rr * 8;
            if (m >= NN) continue;
#pragma unroll
            for (int hh = 0; hh < 2; hh++) {
                int hc = wn * 16 + hh * 8 + tig * 2;
                size_t pb = (size_t)m * 256 + hc;
                float2 pi = *(const float2*)&pre[pb];
                float2 pf = *(const float2*)&pre[pb + 64];
                float2 pg = *(const float2*)&pre[pb + 128];
                float2 po = *(const float2*)&pre[pb + 192];
                size_t hb = (size_t)m * 64 + hc;
                float2 cold = *(const float2*)&g_c[hb];
                float gi0 = acc[mf][0][hh][rr * 2 + 0] + pi.x;
                float gi1 = acc[mf][0][hh][rr * 2 + 1] + pi.y;
                float gf0 = acc[mf][1][hh][rr * 2 + 0] + pf.x;
                float gf1 = acc[mf][1][hh][rr * 2 + 1] + pf.y;
                float gg0 = acc[mf][2][hh][rr * 2 + 0] + pg.x;
                float gg1 = acc[mf][2][hh][rr * 2 + 1] + pg.y;
                float go0 = acc[mf][3][hh][rr * 2 + 0] + po.x;
                float go1 = acc[mf][3][hh][rr * 2 + 1] + po.y;
                float si0 = __fdividef(1.f, 1.f + __expf(-gi0));
                float si1 = __fdividef(1.f, 1.f + __expf(-gi1));
                float sf0 = __fdividef(1.f, 1.f + __expf(-gf0));
                float sf1 = __fdividef(1.f, 1.f + __expf(-gf1));
                float so0 = __fdividef(1.f, 1.f + __expf(-go0));
                float so1 = __fdividef(1.f, 1.f + __expf(-go1));
                float2 cn, hn;
                cn.x = sf0 * cold.x + si0 * tanhf(gg0);
                cn.y = sf1 * cold.y + si1 * tanhf(gg1);
                hn.x = so0 * tanhf(cn.x);
                hn.y = so1 * tanhf(cn.y);
                *(float2*)&g_c[hb] = cn;
                *(float2*)&hout[hb] = hn;
                if (store >= 0) *(float2*)&g_h2last[(size_t)store * NN * 64 + hb] = hn;
            }
        }
}

// ---------------- final projection: out = [xr, h2][-4:] @ W_out + b_out -----------
__global__ __launch_bounds__(256) void k_out(const float* __restrict__ Wout,
                                             const float* __restrict__ bout,
                                             float* __restrict__ out) {
    __shared__ float sX[32][129];
    __shared__ float sW[128][9];
    int tt = blockIdx.y;
    int n0 = blockIdx.x * 32;
    int tid = threadIdx.x;
    for (int i = tid; i < 32 * 64; i += 256) {
        int r = i >> 6, k = i & 63;
        int m = n0 + r;
        sX[r][k] = (m < NN) ? g_xr[((size_t)(TT - 4 + tt) * NN + m) * 64 + k] : 0.f;
        sX[r][64 + k] = (m < NN) ? g_h2last[((size_t)tt * NN + m) * 64 + k] : 0.f;
    }
    for (int i = tid; i < 128 * 8; i += 256) sW[i >> 3][i & 7] = Wout[i];
    __syncthreads();
    int node = tid >> 3, o = tid & 7;
    float acc = bout[o];
    for (int k = 0; k < 128; k++) acc += sX[node][k] * sW[k][o];
    int m = n0 + node;
    if (m < NN) out[((size_t)tt * NN + m) * 8 + o] = acc;
}

// ---------------- misc ------------------------------------------------------------
__global__ void k_zero_state() {
    int i = blockIdx.x * blockDim.x + threadIdx.x;
    if (i < NN * HH) { g_h[0][i] = 0.f; g_c[i] = 0.f; }
}

__global__ void k_copy_c2(float* __restrict__ dst) {
    int i = blockIdx.x * blockDim.x + threadIdx.x;
    if (i < NN * HH) dst[i] = g_c[i];
}

// ---------------- launch ----------------------------------------------------------
extern "C" void kernel_launch(void* const* d_in, const int* in_sizes, int n_in,
                              void* d_out, int out_size) {
    const float* x      = (const float*)d_in[0];
    const int*   ei     = (const int*)d_in[1];
    const float* ew     = (const float*)d_in[2];
    const float* sWr    = (const float*)d_in[3];
    const float* sWroot = (const float*)d_in[4];
    const float* sb     = (const float*)d_in[5];
    const float* Wr1    = (const float*)d_in[6];
    const float* Wroot1 = (const float*)d_in[7];
    const float* b1     = (const float*)d_in[8];
    const float* Wr2    = (const float*)d_in[9];
    const float* Wroot2 = (const float*)d_in[10];
    const float* b2     = (const float*)d_in[11];
    const float* Wout   = (const float*)d_in[12];
    const float* bout   = (const float*)d_in[13];
    float* out = (float*)d_out;
    const int* src = ei;
    const int* dst = ei + EE;

    // CSR build (per launch — deterministic & stateless)
    k_zero_cursor<<<(NN + 255) / 256, 256>>>();
    k_deg<<<(EE + 255) / 256, 256>>>(dst);
    k_scan<<<1, 1024>>>();
    k_fill<<<(EE + 255) / 256, 256>>>(src, dst, ew);

    // SAGE embedding (fp32 for output accuracy)
    dim3 aggGridT(2500, TT);
    k_agg<32><<<aggGridT, 256>>>(0, 0, x);
    k_sage<<<TT * NN / 64, 256>>>(x, sWr, sWroot, sb, out + EMB_OFF);

    // Precompute x-dependent half of all LSTM gates (tf32 tensor cores, parallel T)
    k_agg<64><<<aggGridT, 256>>>(1, 0, nullptr);
    k_pre<<<TT * NN / 128, 512>>>(0, Wr1, Wroot1, b1);
    k_pre<<<TT * NN / 128, 512>>>(1, Wr2, Wroot2, b2);

    // Sequential LSTM steps (LSTM2 continues from LSTM1's final state)
    k_zero_state<<<(NN * HH + 255) / 256, 256>>>();
    int par = 0;
    for (int L = 0; L < 2; L++) {
        const float* Wr = L ? Wr2 : Wr1;
        const float* Wroot = L ? Wroot2 : Wroot1;
        for (int t = 0; t < TT; t++) {
            k_agg<64><<<dim3(2500, 1), 256>>>(2, par, nullptr);
            int store = (L == 1 && t >= TT - 4) ? (t - (TT - 4)) : -1;
            k_cell<<<(NN + 63) / 64, 256>>>(L, t, par, Wr, Wroot, store);
            par ^= 1;
        }
    }

    k_out<<<dim3(NN / 32, 4), 256>>>(Wout, bout, out + OUT_OFF);
    k_copy_c2<<<(NN * HH + 255) / 256, 256>>>(out + C2_OFF);
}

// round 4
// speedup vs baseline: 2.0253x; 1.1277x over previous
#include <cuda_runtime.h>
#include <math.h>

#define TT 12
#define NN 20000
#define EE 400000
#define FF 32
#define HH 64
#define OO 8

// Output layout (flattened tuple): out[4,N,8] | c2[N,64] | emb[T,N,64]
#define OUT_OFF 0
#define C2_OFF  (4*NN*OO)                 // 640000
#define EMB_OFF (C2_OFF + NN*HH)          // 1920000

#define N_TILES ((NN + 63) / 64)          // 313

// ---------------- scratch (static device globals; allocation-free at runtime) ----
__device__ int   g_rowptr[NN + 1];
__device__ int   g_cursor[NN];
__device__ int   g_csr_src[EE];
__device__ float g_csr_w[EE];
__device__ float g_xr[TT * NN * HH];          // relu(emb)
__device__ float g_aggx[TT * NN * FF];        // wmean(x) per t
__device__ float g_aggxr[TT * NN * HH];       // wmean(xr) per t
__device__ float g_pre[2][TT * NN * 4 * HH];  // precomputed gate contributions per LSTM
__device__ float g_h[2][NN * HH];             // ping-pong hidden state
__device__ float g_c[NN * HH];
__device__ float g_aggh[NN * HH];
__device__ float g_h2last[4 * NN * HH];       // h2 for last 4 steps

// grid barrier state
__device__ unsigned g_bar_count = 0;
__device__ volatile unsigned g_bar_gen = 0;

// ---------------- helpers ----------------------------------------------------------
__device__ __forceinline__ unsigned f2tf32(float f) {
    unsigned r;
    asm("cvt.rna.tf32.f32 %0, %1;" : "=r"(r) : "f"(f));
    return r;
}
__device__ __forceinline__ void mma8(float* c, const uint4 a, unsigned b0, unsigned b1) {
    asm volatile(
        "mma.sync.aligned.m16n8k8.row.col.f32.tf32.tf32.f32 "
        "{%0,%1,%2,%3},{%4,%5,%6,%7},{%8,%9},{%0,%1,%2,%3};"
        : "+f"(c[0]), "+f"(c[1]), "+f"(c[2]), "+f"(c[3])
        : "r"(a.x), "r"(a.y), "r"(a.z), "r"(a.w), "r"(b0), "r"(b1));
}
__device__ __forceinline__ unsigned long long pk2(float lo, float hi) {
    unsigned long long r;
    asm("mov.b64 %0, {%1,%2};" : "=l"(r) : "f"(lo), "f"(hi));
    return r;
}
__device__ __forceinline__ void upk2(unsigned long long v, float& lo, float& hi) {
    asm("mov.b64 {%0,%1}, %2;" : "=f"(lo), "=f"(hi) : "l"(v));
}
__device__ __forceinline__ unsigned long long ffma2(unsigned long long a,
                                                    unsigned long long b,
                                                    unsigned long long c) {
    unsigned long long d;
    asm("fma.rn.f32x2 %0, %1, %2, %3;" : "=l"(d) : "l"(a), "l"(b), "l"(c));
    return d;
}
__device__ __forceinline__ unsigned ld_acq(volatile unsigned* p) {
    unsigned v;
    asm volatile("ld.acquire.gpu.u32 %0, [%1];"
                 : "=r"(v) : "l"((const unsigned*)p) : "memory");
    return v;
}
__device__ __forceinline__ void gridbar(unsigned& gen) {
    __syncthreads();
    if (threadIdx.x == 0) {
        __threadfence();
        unsigned t = atomicAdd(&g_bar_count, 1);
        if (t == gridDim.x - 1) {
            g_bar_count = 0;
            __threadfence();
            asm volatile("st.release.gpu.u32 [%0], %1;"
                         :: "l"((unsigned*)&g_bar_gen), "r"(gen + 1) : "memory");
        } else {
            while (ld_acq(&g_bar_gen) != gen + 1) __nanosleep(32);
        }
    }
    gen++;
    __syncthreads();
}

// ---------------- CSR construction ------------------------------------------------
__global__ void k_zero_cursor() {
    int i = blockIdx.x * blockDim.x + threadIdx.x;
    if (i < NN) g_cursor[i] = 0;
}

__global__ void k_deg(const int* __restrict__ dst) {
    int e = blockIdx.x * blockDim.x + threadIdx.x;
    if (e < EE) atomicAdd(&g_cursor[dst[e]], 1);
}

__global__ void k_scan() {
    __shared__ int wsum[32];
    const int CH = 20;
    int tid = threadIdx.x;
    int base = tid * CH;
    int loc[CH];
    int s = 0;
#pragma unroll
    for (int i = 0; i < CH; i++) {
        int idx = base + i;
        int v = (idx < NN) ? g_cursor[idx] : 0;
        loc[i] = s;
        s += v;
    }
    int lane = tid & 31, w = tid >> 5;
    int inc = s;
#pragma unroll
    for (int o = 1; o < 32; o <<= 1) {
        int t = __shfl_up_sync(0xffffffffu, inc, o);
        if (lane >= o) inc += t;
    }
    if (lane == 31) wsum[w] = inc;
    __syncthreads();
    if (w == 0) {
        int v = wsum[lane];
#pragma unroll
        for (int o = 1; o < 32; o <<= 1) {
            int t = __shfl_up_sync(0xffffffffu, v, o);
            if (lane >= o) v += t;
        }
        wsum[lane] = v;
    }
    __syncthreads();
    int excl = inc - s + (w > 0 ? wsum[w - 1] : 0);
#pragma unroll
    for (int i = 0; i < CH; i++) {
        int idx = base + i;
        if (idx < NN) {
            int p = excl + loc[i];
            g_rowptr[idx] = p;
            g_cursor[idx] = p;
        }
    }
    if (tid == 0) g_rowptr[NN] = EE;
}

__global__ void k_fill(const int* __restrict__ src, const int* __restrict__ dst,
                       const float* __restrict__ ew) {
    int e = blockIdx.x * blockDim.x + threadIdx.x;
    if (e < EE) {
        int d = dst[e];
        int pos = atomicAdd(&g_cursor[d], 1);
        g_csr_src[pos] = src[e];
        g_csr_w[pos] = ew[e];
    }
}

// ---------------- weighted-mean aggregation (CSR, warp per node; parallel T) ------
template <int FD>
__global__ void k_agg(int mode, const float* __restrict__ xin) {
    int gw = (blockIdx.x * blockDim.x + threadIdx.x) >> 5;
    int lane = threadIdx.x & 31;
    if (gw >= NN) return;
    size_t toff = (size_t)blockIdx.y * NN * FD;
    const float* __restrict__ in;
    float* __restrict__ out;
    if (mode == 0) { in = xin + toff;   out = g_aggx + toff; }
    else           { in = g_xr + toff;  out = g_aggxr + toff; }

    int e0 = g_rowptr[gw], e1 = g_rowptr[gw + 1];
    float acc[FD / 32];
#pragma unroll
    for (int i = 0; i < FD / 32; i++) acc[i] = 0.f;
    for (int e = e0; e < e1; e++) {
        int s = __ldg(&g_csr_src[e]);
        float w = __ldg(&g_csr_w[e]);
#pragma unroll
        for (int i = 0; i < FD / 32; i++)
            acc[i] += w * __ldg(&in[(size_t)s * FD + lane + 32 * i]);
    }
    float inv = 1.f / (float)max(e1 - e0, 1);
#pragma unroll
    for (int i = 0; i < FD / 32; i++)
        out[(size_t)gw * FD + lane + 32 * i] = acc[i] * inv;
}

// ---------------- SAGE (f32x2 core): emb = aggx@Wr + x@Wroot + b ; xr = relu ------
__global__ __launch_bounds__(256, 2) void k_sage(const float* __restrict__ x,
                                                 const float* __restrict__ Wr,
                                                 const float* __restrict__ Wroot,
                                                 const float* __restrict__ b,
                                                 float* __restrict__ emb) {
    __shared__ float sA[64][33];
    __shared__ float sW[32][66];
    int m0 = blockIdx.x * 64;
    int tid = threadIdx.x;
    int tr = tid / 16, tc = tid % 16;
    unsigned long long acc[4][2];
#pragma unroll
    for (int i = 0; i < 4; i++)
#pragma unroll
        for (int j2 = 0; j2 < 2; j2++) acc[i][j2] = 0ull;
    for (int kb = 0; kb < 2; kb++) {
        const float* Asrc = kb ? x : g_aggx;
        const float* Wsrc = kb ? Wroot : Wr;
        __syncthreads();
        for (int i = tid; i < 64 * 32; i += 256) {
            int r = i >> 5, k = i & 31;
            sA[r][k] = Asrc[(size_t)(m0 + r) * 32 + k];
        }
        for (int i = tid; i < 32 * 64; i += 256) {
            int r = i >> 6, cc = i & 63;
            sW[r][cc] = Wsrc[(size_t)r * 64 + cc];
        }
        __syncthreads();
#pragma unroll
        for (int k = 0; k < 32; k++) {
            unsigned long long a2[4];
#pragma unroll
            for (int i = 0; i < 4; i++) {
                float av = sA[tr * 4 + i][k];
                a2[i] = pk2(av, av);
            }
#pragma unroll
            for (int j2 = 0; j2 < 2; j2++) {
                unsigned long long w2 = *(const unsigned long long*)&sW[k][tc * 4 + j2 * 2];
#pragma unroll
                for (int i = 0; i < 4; i++) acc[i][j2] = ffma2(a2[i], w2, acc[i][j2]);
            }
        }
    }
#pragma unroll
    for (int i = 0; i < 4; i++) {
        size_t mrow = (size_t)(m0 + tr * 4 + i) * 64;
#pragma unroll
        for (int j2 = 0; j2 < 2; j2++) {
            float v0, v1;
            upk2(acc[i][j2], v0, v1);
            int c0 = tc * 4 + j2 * 2;
            v0 += b[c0];
            v1 += b[c0 + 1];
            emb[mrow + c0] = v0;
            emb[mrow + c0 + 1] = v1;
            g_xr[mrow + c0] = fmaxf(v0, 0.f);
            g_xr[mrow + c0 + 1] = fmaxf(v1, 0.f);
        }
    }
}

// ---------------- PRE (tf32 mma): g_pre[L] = [aggxr|xr] @ W[0:64 rows] + b --------
__global__ __launch_bounds__(512, 1) void k_pre(int L, const float* __restrict__ Wr,
                                                const float* __restrict__ Wroot,
                                                const float* __restrict__ bias) {
    __shared__ unsigned sAf[8 * 4 * 32 * 4];
    __shared__ unsigned sWf[4 * 32 * 32 * 2];
    int m0 = blockIdx.x * 128;
    int tid = threadIdx.x;
    int warp = tid >> 5, lane = tid & 31;
    int wm = warp >> 2, wn = warp & 3;
    int gid = lane >> 2, tig = lane & 3;
    float acc[2][4][2][4];
#pragma unroll
    for (int mf = 0; mf < 2; mf++)
#pragma unroll
        for (int g = 0; g < 4; g++)
#pragma unroll
            for (int hh = 0; hh < 2; hh++)
#pragma unroll
                for (int q = 0; q < 4; q++) acc[mf][g][hh][q] = 0.f;

    for (int kb = 0; kb < 4; kb++) {
        const float* Asrc = (kb < 2) ? g_aggxr : g_xr;
        const float* Wsrc = (kb < 2) ? Wr : Wroot;
        int koff = (kb & 1) * 32;
        __syncthreads();
        for (int i = tid; i < 128 * 32; i += 512) {
            int r = i >> 5, c = i & 31;
            float v = Asrc[(size_t)(m0 + r) * 64 + koff + c];
            int slot = ((((r >> 4) * 4 + (c >> 3)) * 32 + ((r & 7) * 4 + (c & 3))) << 2)
                       + (((c >> 2) & 1) * 2 + ((r >> 3) & 1));
            sAf[slot] = f2tf32(v);
        }
        for (int i = tid; i < 32 * 256; i += 512) {
            int k = i >> 8, n = i & 255;
            float v = Wsrc[(size_t)(koff + k) * 256 + n];
            int slot = ((((k >> 3) * 32 + (n >> 3)) * 32 + ((n & 7) * 4 + (k & 3))) << 1)
                       + ((k >> 2) & 1);
            sWf[slot] = f2tf32(v);
        }
        __syncthreads();
#pragma unroll
        for (int kk = 0; kk < 4; kk++) {
            uint4 a[2];
#pragma unroll
            for (int mf = 0; mf < 2; mf++)
                a[mf] = ((const uint4*)sAf)[((wm * 2 + mf) * 4 + kk) * 32 + lane];
#pragma unroll
            for (int g = 0; g < 4; g++)
#pragma unroll
                for (int hh = 0; hh < 2; hh++) {
                    int n8 = g * 8 + wn * 2 + hh;
                    uint2 b = ((const uint2*)sWf)[(kk * 32 + n8) * 32 + lane];
#pragma unroll
                    for (int mf = 0; mf < 2; mf++)
                        mma8(acc[mf][g][hh], a[mf], b.x, b.y);
                }
        }
    }
    float* pre = g_pre[L];
#pragma unroll
    for (int mf = 0; mf < 2; mf++)
#pragma unroll
        for (int rr = 0; rr < 2; rr++) {
            int m = m0 + wm * 32 + mf * 16 + gid + rr * 8;
#pragma unroll
            for (int g = 0; g < 4; g++)
#pragma unroll
                for (int hh = 0; hh < 2; hh++) {
                    int n0 = g * 64 + wn * 16 + hh * 8 + tig * 2;
                    float2 bv = *(const float2*)&bias[n0];
                    float2 v;
                    v.x = acc[mf][g][hh][rr * 2 + 0] + bv.x;
                    v.y = acc[mf][g][hh][rr * 2 + 1] + bv.y;
                    *(float2*)&pre[(size_t)m * 256 + n0] = v;
                }
        }
}

// ---------------- persistent fused LSTM chain -------------------------------------
// One launch runs: h0/c0 init, both layers x 12 steps (agg + cell), c2 copy.
// grid = #SMs, 512 threads, 160KB dyn smem (forces 1 block/SM -> all resident).
// smem: sWf [16 kchunks][32 n8][32 lane][2] tf32 weights (per layer),
//       sA  [4 mfrag][16 kchunk][32 lane][4] tf32 A tile.
#define CHAIN_SMEM ((16 * 32 * 32 * 2 + 4 * 16 * 32 * 4) * 4)

__global__ __launch_bounds__(512, 1) void k_chain(const float* __restrict__ Wr1,
                                                  const float* __restrict__ Wroot1,
                                                  const float* __restrict__ Wr2,
                                                  const float* __restrict__ Wroot2,
                                                  float* __restrict__ outC2) {
    extern __shared__ unsigned smem[];
    unsigned* sWf = smem;                    // 32768 u32
    unsigned* sA = smem + 16 * 32 * 32 * 2;  // 8192 u32
    int tid = threadIdx.x;
    int warp = tid >> 5, lane = tid & 31;
    int wm = warp >> 3, wn = warp & 7;       // 2 x 8 warp grid over 64x256 tile
    int gid = lane >> 2, tig = lane & 3;
    unsigned gen = g_bar_gen;

    // init h0 = 0, c0 = 0
    for (int i = blockIdx.x * 512 + tid; i < NN * HH; i += gridDim.x * 512) {
        g_h[0][i] = 0.f;
        g_c[i] = 0.f;
    }
    gridbar(gen);

    int par = 0;
    for (int L = 0; L < 2; L++) {
        const float* __restrict__ Wr = L ? Wr2 : Wr1;
        const float* __restrict__ Wroot = L ? Wroot2 : Wroot1;
        // stage gate weights (h-part rows) fragment-major tf32, once per layer
        for (int i = tid; i < 128 * 256; i += 512) {
            int kg = i >> 8, n = i & 255;
            float v = (kg < 64) ? Wr[(size_t)(64 + kg) * 256 + n]
                                : Wroot[(size_t)kg * 256 + n];
            int slot = ((((kg >> 3) * 32 + (n >> 3)) * 32 + ((n & 7) * 4 + (kg & 3))) << 1)
                       + ((kg >> 2) & 1);
            sWf[slot] = f2tf32(v);
        }
        __syncthreads();
        const float* __restrict__ preL = g_pre[L];

        for (int t = 0; t < TT; t++) {
            const float* __restrict__ hin = g_h[par];
            float* __restrict__ hout = g_h[par ^ 1];
            // ---- agg phase: g_aggh = wmean(hin) ----
            const float2* __restrict__ hin2 = (const float2*)hin;
            float2* __restrict__ agg2 = (float2*)g_aggh;
            for (int nd = blockIdx.x * 16 + warp; nd < NN; nd += gridDim.x * 16) {
                int e0 = g_rowptr[nd], e1 = g_rowptr[nd + 1];
                float ax = 0.f, ay = 0.f;
                for (int e = e0; e < e1; e++) {
                    int s = __ldg(&g_csr_src[e]);
                    float w = __ldg(&g_csr_w[e]);
                    float2 v = __ldg(&hin2[(size_t)s * 32 + lane]);
                    ax += w * v.x;
                    ay += w * v.y;
                }
                float inv = 1.f / (float)max(e1 - e0, 1);
                float2 o;
                o.x = ax * inv;
                o.y = ay * inv;
                agg2[(size_t)nd * 32 + lane] = o;
            }
            gridbar(gen);

            // ---- cell phase ----
            const float* __restrict__ pre = preL + (size_t)t * NN * 256;
            int store = (L == 1 && t >= TT - 4) ? (t - (TT - 4)) : -1;
            for (int tile = blockIdx.x; tile < N_TILES; tile += gridDim.x) {
                int m0 = tile * 64;
                __syncthreads();
                // stage A = [aggh | hin] (64 x 128) fragment-major tf32
                for (int i = tid; i < 64 * 128; i += 512) {
                    int r = i >> 7, c = i & 127;
                    int m = m0 + r;
                    float v = 0.f;
                    if (m < NN)
                        v = (c < 64) ? g_aggh[(size_t)m * 64 + c]
                                     : hin[(size_t)m * 64 + (c - 64)];
                    int slot = ((((r >> 4) * 16 + (c >> 3)) * 32 + ((r & 7) * 4 + (c & 3))) << 2)
                               + (((c >> 2) & 1) * 2 + ((r >> 3) & 1));
                    sA[slot] = f2tf32(v);
                }
                __syncthreads();
                float acc[2][4][4];
#pragma unroll
                for (int mf = 0; mf < 2; mf++)
#pragma unroll
                    for (int g = 0; g < 4; g++)
#pragma unroll
                        for (int q = 0; q < 4; q++) acc[mf][g][q] = 0.f;
#pragma unroll
                for (int kc = 0; kc < 16; kc++) {
                    uint4 a[2];
#pragma unroll
                    for (int mf = 0; mf < 2; mf++)
                        a[mf] = ((const uint4*)sA)[((wm * 2 + mf) * 16 + kc) * 32 + lane];
#pragma unroll
                    for (int g = 0; g < 4; g++) {
                        int n8 = g * 8 + wn;
                        uint2 b = ((const uint2*)sWf)[(kc * 32 + n8) * 32 + lane];
#pragma unroll
                        for (int mf = 0; mf < 2; mf++)
                            mma8(acc[mf][g], a[mf], b.x, b.y);
                    }
                }
                // pointwise: gates -> c,h
#pragma unroll
                for (int mf = 0; mf < 2; mf++)
#pragma unroll
                    for (int rr = 0; rr < 2; rr++) {
                        int m = m0 + wm * 32 + mf * 16 + gid + rr * 8;
                        if (m >= NN) continue;
                        int hc = wn * 8 + tig * 2;
                        size_t pb = (size_t)m * 256 + hc;
                        float2 pi = *(const float2*)&pre[pb];
                        float2 pf = *(const float2*)&pre[pb + 64];
                        float2 pg = *(const float2*)&pre[pb + 128];
                        float2 po = *(const float2*)&pre[pb + 192];
                        size_t hb = (size_t)m * 64 + hc;
                        float2 cold = *(const float2*)&g_c[hb];
                        float gi0 = acc[mf][0][rr * 2 + 0] + pi.x;
                        float gi1 = acc[mf][0][rr * 2 + 1] + pi.y;
                        float gf0 = acc[mf][1][rr * 2 + 0] + pf.x;
                        float gf1 = acc[mf][1][rr * 2 + 1] + pf.y;
                        float gg0 = acc[mf][2][rr * 2 + 0] + pg.x;
                        float gg1 = acc[mf][2][rr * 2 + 1] + pg.y;
                        float go0 = acc[mf][3][rr * 2 + 0] + po.x;
                        float go1 = acc[mf][3][rr * 2 + 1] + po.y;
                        float si0 = __fdividef(1.f, 1.f + __expf(-gi0));
                        float si1 = __fdividef(1.f, 1.f + __expf(-gi1));
                        float sf0 = __fdividef(1.f, 1.f + __expf(-gf0));
                        float sf1 = __fdividef(1.f, 1.f + __expf(-gf1));
                        float so0 = __fdividef(1.f, 1.f + __expf(-go0));
                        float so1 = __fdividef(1.f, 1.f + __expf(-go1));
                        float2 cn, hn;
                        cn.x = sf0 * cold.x + si0 * tanhf(gg0);
                        cn.y = sf1 * cold.y + si1 * tanhf(gg1);
                        hn.x = so0 * tanhf(cn.x);
                        hn.y = so1 * tanhf(cn.y);
                        *(float2*)&g_c[hb] = cn;
                        *(float2*)&hout[hb] = hn;
                        if (store >= 0)
                            *(float2*)&g_h2last[(size_t)store * NN * 64 + hb] = hn;
                    }
            }
            gridbar(gen);
            par ^= 1;
        }
        __syncthreads();  // before re-staging sWf for next layer
    }

    // c2 copy
    for (int i = blockIdx.x * 512 + tid; i < NN * HH; i += gridDim.x * 512)
        outC2[i] = g_c[i];
}

// ---------------- final projection: out = [xr, h2][-4:] @ W_out + b_out -----------
__global__ __launch_bounds__(256) void k_out(const float* __restrict__ Wout,
                                             const float* __restrict__ bout,
                                             float* __restrict__ out) {
    __shared__ float sX[32][129];
    __shared__ float sW[128][9];
    int tt = blockIdx.y;
    int n0 = blockIdx.x * 32;
    int tid = threadIdx.x;
    for (int i = tid; i < 32 * 64; i += 256) {
        int r = i >> 6, k = i & 63;
        int m = n0 + r;
        sX[r][k] = (m < NN) ? g_xr[((size_t)(TT - 4 + tt) * NN + m) * 64 + k] : 0.f;
        sX[r][64 + k] = (m < NN) ? g_h2last[((size_t)tt * NN + m) * 64 + k] : 0.f;
    }
    for (int i = tid; i < 128 * 8; i += 256) sW[i >> 3][i & 7] = Wout[i];
    __syncthreads();
    int node = tid >> 3, o = tid & 7;
    float acc = bout[o];
    for (int k = 0; k < 128; k++) acc += sX[node][k] * sW[k][o];
    int m = n0 + node;
    if (m < NN) out[((size_t)tt * NN + m) * 8 + o] = acc;
}

// ---------------- launch ----------------------------------------------------------
extern "C" void kernel_launch(void* const* d_in, const int* in_sizes, int n_in,
                              void* d_out, int out_size) {
    const float* x      = (const float*)d_in[0];
    const int*   ei     = (const int*)d_in[1];
    const float* ew     = (const float*)d_in[2];
    const float* sWr    = (const float*)d_in[3];
    const float* sWroot = (const float*)d_in[4];
    const float* sb     = (const float*)d_in[5];
    const float* Wr1    = (const float*)d_in[6];
    const float* Wroot1 = (const float*)d_in[7];
    const float* b1     = (const float*)d_in[8];
    const float* Wr2    = (const float*)d_in[9];
    const float* Wroot2 = (const float*)d_in[10];
    const float* b2     = (const float*)d_in[11];
    const float* Wout   = (const float*)d_in[12];
    const float* bout   = (const float*)d_in[13];
    float* out = (float*)d_out;
    const int* src = ei;
    const int* dst = ei + EE;

    int nsm = 0;
    cudaDeviceGetAttribute(&nsm, cudaDevAttrMultiProcessorCount, 0);
    cudaFuncSetAttribute(k_chain, cudaFuncAttributeMaxDynamicSharedMemorySize,
                         CHAIN_SMEM);

    // CSR build (per launch — deterministic & stateless)
    k_zero_cursor<<<(NN + 255) / 256, 256>>>();
    k_deg<<<(EE + 255) / 256, 256>>>(dst);
    k_scan<<<1, 1024>>>();
    k_fill<<<(EE + 255) / 256, 256>>>(src, dst, ew);

    // SAGE embedding (exact fp32, f32x2 core)
    dim3 aggGridT(2500, TT);
    k_agg<32><<<aggGridT, 256>>>(0, x);
    k_sage<<<TT * NN / 64, 256>>>(x, sWr, sWroot, sb, out + EMB_OFF);

    // Precompute x-dependent half of all LSTM gates (tf32 tensor cores, parallel T)
    k_agg<64><<<aggGridT, 256>>>(1, nullptr);
    k_pre<<<TT * NN / 128, 512>>>(0, Wr1, Wroot1, b1);
    k_pre<<<TT * NN / 128, 512>>>(1, Wr2, Wroot2, b2);

    // Fused persistent chain: both LSTMs, 24 steps, init + c2 copy inside
    k_chain<<<nsm, 512, CHAIN_SMEM>>>(Wr1, Wroot1, Wr2, Wroot2, out + C2_OFF);

    k_out<<<dim3(NN / 32, 4), 256>>>(Wout, bout, out + OUT_OFF);
}

// round 5
// speedup vs baseline: 2.2886x; 1.1300x over previous
#include <cuda_runtime.h>
#include <cuda_fp16.h>
#include <math.h>

#define TT 12
#define NN 20000
#define EE 400000
#define FF 32
#define HH 64
#define OO 8

// Output layout (flattened tuple): out[4,N,8] | c2[N,64] | emb[T,N,64]
#define OUT_OFF 0
#define C2_OFF  (4*NN*OO)                 // 640000
#define EMB_OFF (C2_OFF + NN*HH)          // 1920000

#define N_TILES ((NN + 63) / 64)          // 313
#define PRE_TILES (TT * NN / 128)         // 1875

// ---------------- scratch (static device globals; allocation-free at runtime) ----
__device__ int      g_rowptr[NN + 1];
__device__ int      g_cursor[NN];
__device__ int      g_csr_src[EE];
__device__ float    g_csr_w[EE];
__device__ float    g_xr[TT * NN * HH];          // relu(emb)
__device__ float    g_aggx[TT * NN * FF];        // wmean(x) per t
__device__ float    g_aggxr[TT * NN * HH];       // wmean(xr) per t
__device__ float    g_pre[2][TT * NN * 4 * HH];  // precomputed gate contributions
__device__ unsigned g_hh[2][NN * 32];            // fp16 hidden state (half2 words)
__device__ float    g_c[NN * HH];
__device__ float    g_h2last[4 * NN * HH];       // h2 for last 4 steps (fp32)

// grid barrier state
__device__ unsigned g_bar_count = 0;
__device__ volatile unsigned g_bar_gen = 0;

// ---------------- helpers ----------------------------------------------------------
__device__ __forceinline__ void mma16(float* c, const uint4 a, const uint2 b) {
    asm volatile(
        "mma.sync.aligned.m16n8k16.row.col.f32.f16.f16.f32 "
        "{%0,%1,%2,%3},{%4,%5,%6,%7},{%8,%9},{%0,%1,%2,%3};"
        : "+f"(c[0]), "+f"(c[1]), "+f"(c[2]), "+f"(c[3])
        : "r"(a.x), "r"(a.y), "r"(a.z), "r"(a.w), "r"(b.x), "r"(b.y));
}
__device__ __forceinline__ unsigned h2u(float lo, float hi) {
    __half2 h = __floats2half2_rn(lo, hi);
    return *(unsigned*)&h;
}
__device__ __forceinline__ unsigned long long pk2(float lo, float hi) {
    unsigned long long r;
    asm("mov.b64 %0, {%1,%2};" : "=l"(r) : "f"(lo), "f"(hi));
    return r;
}
__device__ __forceinline__ void upk2(unsigned long long v, float& lo, float& hi) {
    asm("mov.b64 {%0,%1}, %2;" : "=f"(lo), "=f"(hi) : "l"(v));
}
__device__ __forceinline__ unsigned long long ffma2(unsigned long long a,
                                                    unsigned long long b,
                                                    unsigned long long c) {
    unsigned long long d;
    asm("fma.rn.f32x2 %0, %1, %2, %3;" : "=l"(d) : "l"(a), "l"(b), "l"(c));
    return d;
}
__device__ __forceinline__ unsigned ld_acq(volatile unsigned* p) {
    unsigned v;
    asm volatile("ld.acquire.gpu.u32 %0, [%1];"
                 : "=r"(v) : "l"((const unsigned*)p) : "memory");
    return v;
}
__device__ __forceinline__ void gridbar(unsigned& gen) {
    __syncthreads();
    if (threadIdx.x == 0) {
        __threadfence();
        unsigned t = atomicAdd(&g_bar_count, 1);
        if (t == gridDim.x - 1) {
            g_bar_count = 0;
            __threadfence();
            asm volatile("st.release.gpu.u32 [%0], %1;"
                         :: "l"((unsigned*)&g_bar_gen), "r"(gen + 1) : "memory");
        } else {
            while (ld_acq(&g_bar_gen) != gen + 1) __nanosleep(32);
        }
    }
    gen++;
    __syncthreads();
}

// fragment-major smem slot helpers (fp16 m16n8k16)
// A: uint per (r,c-pair): chunk (mf=r>>4, kc=c>>4), lane=(r&7)*4+((c&7)>>1),
//    reg = ((c>>3)&1)*2 + ((r>>3)&1)
// W: uint per (k-pair, n): chunk (kc=k>>4, n8=n>>3), lane=(n&7)*4+((k&7)>>1),
//    breg = (k>>3)&1

// ---------------- CSR construction ------------------------------------------------
__global__ void k_zero_cursor() {
    int i = blockIdx.x * blockDim.x + threadIdx.x;
    if (i < NN) g_cursor[i] = 0;
}

__global__ void k_deg(const int* __restrict__ dst) {
    int e = blockIdx.x * blockDim.x + threadIdx.x;
    if (e < EE) atomicAdd(&g_cursor[dst[e]], 1);
}

__global__ void k_scan() {
    __shared__ int wsum[32];
    const int CH = 20;
    int tid = threadIdx.x;
    int base = tid * CH;
    int loc[CH];
    int s = 0;
#pragma unroll
    for (int i = 0; i < CH; i++) {
        int idx = base + i;
        int v = (idx < NN) ? g_cursor[idx] : 0;
        loc[i] = s;
        s += v;
    }
    int lane = tid & 31, w = tid >> 5;
    int inc = s;
#pragma unroll
    for (int o = 1; o < 32; o <<= 1) {
        int t = __shfl_up_sync(0xffffffffu, inc, o);
        if (lane >= o) inc += t;
    }
    if (lane == 31) wsum[w] = inc;
    __syncthreads();
    if (w == 0) {
        int v = wsum[lane];
#pragma unroll
        for (int o = 1; o < 32; o <<= 1) {
            int t = __shfl_up_sync(0xffffffffu, v, o);
            if (lane >= o) v += t;
        }
        wsum[lane] = v;
    }
    __syncthreads();
    int excl = inc - s + (w > 0 ? wsum[w - 1] : 0);
#pragma unroll
    for (int i = 0; i < CH; i++) {
        int idx = base + i;
        if (idx < NN) {
            int p = excl + loc[i];
            g_rowptr[idx] = p;
            g_cursor[idx] = p;
        }
    }
    if (tid == 0) g_rowptr[NN] = EE;
}

__global__ void k_fill(const int* __restrict__ src, const int* __restrict__ dst,
                       const float* __restrict__ ew) {
    int e = blockIdx.x * blockDim.x + threadIdx.x;
    if (e < EE) {
        int d = dst[e];
        int pos = atomicAdd(&g_cursor[d], 1);
        g_csr_src[pos] = src[e];
        g_csr_w[pos] = ew[e];
    }
}

// ---------------- weighted-mean aggregation (CSR, warp per node; parallel T) ------
template <int FD>
__global__ void k_agg(int mode, const float* __restrict__ xin) {
    int gw = (blockIdx.x * blockDim.x + threadIdx.x) >> 5;
    int lane = threadIdx.x & 31;
    if (gw >= NN) return;
    size_t toff = (size_t)blockIdx.y * NN * FD;
    const float* __restrict__ in;
    float* __restrict__ out;
    if (mode == 0) { in = xin + toff;   out = g_aggx + toff; }
    else           { in = g_xr + toff;  out = g_aggxr + toff; }

    int e0 = g_rowptr[gw], e1 = g_rowptr[gw + 1];
    float acc[FD / 32];
#pragma unroll
    for (int i = 0; i < FD / 32; i++) acc[i] = 0.f;
    for (int e = e0; e < e1; e++) {
        int s = __ldg(&g_csr_src[e]);
        float w = __ldg(&g_csr_w[e]);
#pragma unroll
        for (int i = 0; i < FD / 32; i++)
            acc[i] += w * __ldg(&in[(size_t)s * FD + lane + 32 * i]);
    }
    float inv = 1.f / (float)max(e1 - e0, 1);
#pragma unroll
    for (int i = 0; i < FD / 32; i++)
        out[(size_t)gw * FD + lane + 32 * i] = acc[i] * inv;
}

// ---------------- SAGE (f32x2 core, exact fp32): emb; xr = relu -------------------
__global__ __launch_bounds__(256, 2) void k_sage(const float* __restrict__ x,
                                                 const float* __restrict__ Wr,
                                                 const float* __restrict__ Wroot,
                                                 const float* __restrict__ b,
                                                 float* __restrict__ emb) {
    __shared__ float sA[64][33];
    __shared__ float sW[32][66];
    int m0 = blockIdx.x * 64;
    int tid = threadIdx.x;
    int tr = tid / 16, tc = tid % 16;
    unsigned long long acc[4][2];
#pragma unroll
    for (int i = 0; i < 4; i++)
#pragma unroll
        for (int j2 = 0; j2 < 2; j2++) acc[i][j2] = 0ull;
    for (int kb = 0; kb < 2; kb++) {
        const float* Asrc = kb ? x : g_aggx;
        const float* Wsrc = kb ? Wroot : Wr;
        __syncthreads();
        for (int i = tid; i < 64 * 32; i += 256) {
            int r = i >> 5, k = i & 31;
            sA[r][k] = Asrc[(size_t)(m0 + r) * 32 + k];
        }
        for (int i = tid; i < 32 * 64; i += 256) {
            int r = i >> 6, cc = i & 63;
            sW[r][cc] = Wsrc[(size_t)r * 64 + cc];
        }
        __syncthreads();
#pragma unroll
        for (int k = 0; k < 32; k++) {
            unsigned long long a2[4];
#pragma unroll
            for (int i = 0; i < 4; i++) {
                float av = sA[tr * 4 + i][k];
                a2[i] = pk2(av, av);
            }
#pragma unroll
            for (int j2 = 0; j2 < 2; j2++) {
                unsigned long long w2 = *(const unsigned long long*)&sW[k][tc * 4 + j2 * 2];
#pragma unroll
                for (int i = 0; i < 4; i++) acc[i][j2] = ffma2(a2[i], w2, acc[i][j2]);
            }
        }
    }
#pragma unroll
    for (int i = 0; i < 4; i++) {
        size_t mrow = (size_t)(m0 + tr * 4 + i) * 64;
#pragma unroll
        for (int j2 = 0; j2 < 2; j2++) {
            float v0, v1;
            upk2(acc[i][j2], v0, v1);
            int c0 = tc * 4 + j2 * 2;
            v0 += b[c0];
            v1 += b[c0 + 1];
            emb[mrow + c0] = v0;
            emb[mrow + c0 + 1] = v1;
            g_xr[mrow + c0] = fmaxf(v0, 0.f);
            g_xr[mrow + c0 + 1] = fmaxf(v1, 0.f);
        }
    }
}

// ---------------- persistent PRE (fp16 mma): both layers, W staged once/SM --------
// pre[L] = [aggxr|xr](128 rows/tile, K=128) @ [Wr[0:64];Wroot[0:64]](fp16) + b
// smem: sW 16384 u32 (64KB) + sA 8192 u32 (32KB) = 96KB.
#define PRE_SMEM ((8 * 32 * 32 * 2 + 8 * 8 * 32 * 4) * 4)
__global__ __launch_bounds__(512, 1) void k_pre(const float* __restrict__ Wr1,
                                                const float* __restrict__ Wroot1,
                                                const float* __restrict__ b1,
                                                const float* __restrict__ Wr2,
                                                const float* __restrict__ Wroot2,
                                                const float* __restrict__ b2) {
    extern __shared__ unsigned smem[];
    unsigned* sW = smem;                      // [(kc*32+n8)*32+lane]*2+breg
    unsigned* sA = smem + 8 * 32 * 32 * 2;    // [((mf*8+kc)*32+lane)*4+reg]
    int tid = threadIdx.x;
    int warp = tid >> 5, lane = tid & 31;
    int wm = warp >> 2, wn = warp & 3;        // 4 x 4 warps over 128x256
    int gid = lane >> 2, tig = lane & 3;

    for (int L = 0; L < 2; L++) {
        const float* __restrict__ Wr = L ? Wr2 : Wr1;
        const float* __restrict__ Wroot = L ? Wroot2 : Wroot1;
        const float* __restrict__ bias = L ? b2 : b1;
        float* __restrict__ pre = g_pre[L];
        __syncthreads();
        // stage W fp16 fragment-major: k<64 -> Wr rows[0:64], else Wroot rows[0:64]
        for (int i = tid; i < 64 * 256; i += 512) {
            int k2 = i >> 8, n = i & 255;
            int k = k2 * 2;
            float v0, v1;
            if (k < 64) {
                v0 = Wr[(size_t)k * 256 + n];
                v1 = Wr[(size_t)(k + 1) * 256 + n];
            } else {
                v0 = Wroot[(size_t)(k - 64) * 256 + n];
                v1 = Wroot[(size_t)(k - 63) * 256 + n];
            }
            int kc = k2 >> 3, breg = (k2 >> 2) & 1;
            int bl = (n & 7) * 4 + (k2 & 3);
            sW[((kc * 32 + (n >> 3)) * 32 + bl) * 2 + breg] = h2u(v0, v1);
        }
        __syncthreads();

        for (int tile = blockIdx.x; tile < PRE_TILES; tile += gridDim.x) {
            int m0 = tile * 128;
            __syncthreads();
            // stage A: rows 128, cols: [0,64)=aggxr, [64,128)=xr   (fp16 pairs)
            for (int i = tid; i < 128 * 64; i += 512) {
                int r = i >> 6, c2 = i & 63;
                int c = c2 * 2;
                size_t mrow = (size_t)(m0 + r) * 64;
                float v0, v1;
                if (c < 64) {
                    v0 = g_aggxr[mrow + c];
                    v1 = g_aggxr[mrow + c + 1];
                } else {
                    v0 = g_xr[mrow + c - 64];
                    v1 = g_xr[mrow + c - 63];
                }
                int mf = r >> 4, kc = c2 >> 3;
                int reg = ((c2 >> 2) & 1) * 2 + ((r >> 3) & 1);
                int al = (r & 7) * 4 + (c2 & 3);
                sA[((mf * 8 + kc) * 32 + al) * 4 + reg] = h2u(v0, v1);
            }
            __syncthreads();
            float acc[2][4][2][4];
#pragma unroll
            for (int mf = 0; mf < 2; mf++)
#pragma unroll
                for (int g = 0; g < 4; g++)
#pragma unroll
                    for (int hh = 0; hh < 2; hh++)
#pragma unroll
                        for (int q = 0; q < 4; q++) acc[mf][g][hh][q] = 0.f;
#pragma unroll
            for (int kc = 0; kc < 8; kc++) {
                uint4 a[2];
#pragma unroll
                for (int mf = 0; mf < 2; mf++)
                    a[mf] = ((const uint4*)sA)[((wm * 2 + mf) * 8 + kc) * 32 + lane];
#pragma unroll
                for (int g = 0; g < 4; g++)
#pragma unroll
                    for (int hh = 0; hh < 2; hh++) {
                        int n8 = g * 8 + wn * 2 + hh;
                        uint2 b = ((const uint2*)sW)[(kc * 32 + n8) * 32 + lane];
#pragma unroll
                        for (int mf = 0; mf < 2; mf++)
                            mma16(acc[mf][g][hh], a[mf], b);
                    }
            }
#pragma unroll
            for (int mf = 0; mf < 2; mf++)
#pragma unroll
                for (int rr = 0; rr < 2; rr++) {
                    int m = m0 + wm * 32 + mf * 16 + gid + rr * 8;
#pragma unroll
                    for (int g = 0; g < 4; g++)
#pragma unroll
                        for (int hh = 0; hh < 2; hh++) {
                            int n0 = g * 64 + wn * 16 + hh * 8 + tig * 2;
                            float2 bv = *(const float2*)&bias[n0];
                            float2 v;
                            v.x = acc[mf][g][hh][rr * 2 + 0] + bv.x;
                            v.y = acc[mf][g][hh][rr * 2 + 1] + bv.y;
                            *(float2*)&pre[(size_t)m * 256 + n0] = v;
                        }
                }
        }
    }
}

// ---------------- persistent fused LSTM chain (fp16 h, fused agg+cell) ------------
// One barrier per step. smem: sW 64KB + sA 16KB = 80KB (request 160KB -> 1 blk/SM).
#define CHAIN_SMEM (160 * 1024)
__global__ __launch_bounds__(512, 1) void k_chain(const float* __restrict__ Wr1,
                                                  const float* __restrict__ Wroot1,
                                                  const float* __restrict__ Wr2,
                                                  const float* __restrict__ Wroot2,
                                                  float* __restrict__ outC2) {
    extern __shared__ unsigned smem[];
    unsigned* sW = smem;                      // 16384 u32
    unsigned* sA = smem + 8 * 32 * 32 * 2;    // 4096 u32
    int tid = threadIdx.x;
    int warp = tid >> 5, lane = tid & 31;
    int wm = warp >> 3, wn = warp & 7;        // 2 x 8 warps over 64x256
    int gid = lane >> 2, tig = lane & 3;
    unsigned gen = g_bar_gen;

    // init h0 = 0 (fp16), c0 = 0
    for (int i = blockIdx.x * 512 + tid; i < NN * 32; i += gridDim.x * 512)
        g_hh[0][i] = 0u;
    for (int i = blockIdx.x * 512 + tid; i < NN * HH; i += gridDim.x * 512)
        g_c[i] = 0.f;
    gridbar(gen);

    int par = 0;
    for (int L = 0; L < 2; L++) {
        const float* __restrict__ Wr = L ? Wr2 : Wr1;
        const float* __restrict__ Wroot = L ? Wroot2 : Wroot1;
        // stage gate weights (h-part rows 64..127 of Wr / Wroot) fp16 frag-major
        for (int i = tid; i < 64 * 256; i += 512) {
            int k2 = i >> 8, n = i & 255;
            int k = k2 * 2;
            float v0, v1;
            if (k < 64) {
                v0 = Wr[(size_t)(64 + k) * 256 + n];
                v1 = Wr[(size_t)(65 + k) * 256 + n];
            } else {
                v0 = Wroot[(size_t)k * 256 + n];
                v1 = Wroot[(size_t)(k + 1) * 256 + n];
            }
            int kc = k2 >> 3, breg = (k2 >> 2) & 1;
            int bl = (n & 7) * 4 + (k2 & 3);
            sW[((kc * 32 + (n >> 3)) * 32 + bl) * 2 + breg] = h2u(v0, v1);
        }
        __syncthreads();
        const float* __restrict__ preL = g_pre[L];

        for (int t = 0; t < TT; t++) {
            const unsigned* __restrict__ hin = g_hh[par];
            unsigned* __restrict__ hout = g_hh[par ^ 1];
            const float* __restrict__ pre = preL + (size_t)t * NN * 256;
            int store = (L == 1 && t >= TT - 4) ? (t - (TT - 4)) : -1;

            for (int tile = blockIdx.x; tile < N_TILES; tile += gridDim.x) {
                int m0 = tile * 64;
                __syncthreads();
                // fused agg + A staging: warp handles 4 nodes; lane = feat pair 2l,2l+1
#pragma unroll
                for (int rq = 0; rq < 4; rq++) {
                    int r = warp * 4 + rq;
                    int m = m0 + r;
                    unsigned aggu = 0u, hu = 0u;
                    if (m < NN) {
                        int e0 = g_rowptr[m], e1 = g_rowptr[m + 1];
                        float ax = 0.f, ay = 0.f;
                        for (int e = e0; e < e1; e++) {
                            int s = __ldg(&g_csr_src[e]);
                            float w = __ldg(&g_csr_w[e]);
                            unsigned u = __ldg(&hin[(size_t)s * 32 + lane]);
                            float2 v = __half22float2(*(const __half2*)&u);
                            ax += w * v.x;
                            ay += w * v.y;
                        }
                        float inv = 1.f / (float)max(e1 - e0, 1);
                        aggu = h2u(ax * inv, ay * inv);
                        hu = hin[(size_t)m * 32 + lane];
                    }
                    int mf = r >> 4;
                    int reg_base = (r >> 3) & 1;
                    int al = (r & 7) * 4 + (lane & 3);
                    int regc = ((lane >> 2) & 1) * 2 + reg_base;
                    int kcA = lane >> 3;           // agg part cols [0,64)
                    sA[((mf * 8 + kcA) * 32 + al) * 4 + regc] = aggu;
                    sA[((mf * 8 + 4 + kcA) * 32 + al) * 4 + regc] = hu;  // h part
                }
                __syncthreads();
                float acc[2][4][4];
#pragma unroll
                for (int mf = 0; mf < 2; mf++)
#pragma unroll
                    for (int g = 0; g < 4; g++)
#pragma unroll
                        for (int q = 0; q < 4; q++) acc[mf][g][q] = 0.f;
#pragma unroll
                for (int kc = 0; kc < 8; kc++) {
                    uint4 a[2];
#pragma unroll
                    for (int mf = 0; mf < 2; mf++)
                        a[mf] = ((const uint4*)sA)[((wm * 2 + mf) * 8 + kc) * 32 + lane];
#pragma unroll
                    for (int g = 0; g < 4; g++) {
                        int n8 = g * 8 + wn;
                        uint2 b = ((const uint2*)sW)[(kc * 32 + n8) * 32 + lane];
#pragma unroll
                        for (int mf = 0; mf < 2; mf++)
                            mma16(acc[mf][g], a[mf], b);
                    }
                }
                // pointwise
#pragma unroll
                for (int mf = 0; mf < 2; mf++)
#pragma unroll
                    for (int rr = 0; rr < 2; rr++) {
                        int m = m0 + wm * 32 + mf * 16 + gid + rr * 8;
                        if (m >= NN) continue;
                        int hc = wn * 8 + tig * 2;
                        size_t pb = (size_t)m * 256 + hc;
                        float2 pi = *(const float2*)&pre[pb];
                        float2 pf = *(const float2*)&pre[pb + 64];
                        float2 pg = *(const float2*)&pre[pb + 128];
                        float2 po = *(const float2*)&pre[pb + 192];
                        size_t hb = (size_t)m * 64 + hc;
                        float2 cold = *(const float2*)&g_c[hb];
                        float gi0 = acc[mf][0][rr * 2 + 0] + pi.x;
                        float gi1 = acc[mf][0][rr * 2 + 1] + pi.y;
                        float gf0 = acc[mf][1][rr * 2 + 0] + pf.x;
                        float gf1 = acc[mf][1][rr * 2 + 1] + pf.y;
                        float gg0 = acc[mf][2][rr * 2 + 0] + pg.x;
                        float gg1 = acc[mf][2][rr * 2 + 1] + pg.y;
                        float go0 = acc[mf][3][rr * 2 + 0] + po.x;
                        float go1 = acc[mf][3][rr * 2 + 1] + po.y;
                        float si0 = __fdividef(1.f, 1.f + __expf(-gi0));
                        float si1 = __fdividef(1.f, 1.f + __expf(-gi1));
                        float sf0 = __fdividef(1.f, 1.f + __expf(-gf0));
                        float sf1 = __fdividef(1.f, 1.f + __expf(-gf1));
                        float so0 = __fdividef(1.f, 1.f + __expf(-go0));
                        float so1 = __fdividef(1.f, 1.f + __expf(-go1));
                        float2 cn, hn;
                        cn.x = sf0 * cold.x + si0 * tanhf(gg0);
                        cn.y = sf1 * cold.y + si1 * tanhf(gg1);
                        hn.x = so0 * tanhf(cn.x);
                        hn.y = so1 * tanhf(cn.y);
                        *(float2*)&g_c[hb] = cn;
                        hout[(size_t)m * 32 + (hc >> 1)] = h2u(hn.x, hn.y);
                        if (store >= 0)
                            *(float2*)&g_h2last[(size_t)store * NN * 64 + hb] = hn;
                    }
            }
            gridbar(gen);
            par ^= 1;
        }
        __syncthreads();  // before re-staging sW for next layer
    }

    // c2 copy
    for (int i = blockIdx.x * 512 + tid; i < NN * HH; i += gridDim.x * 512)
        outC2[i] = g_c[i];
}

// ---------------- final projection: out = [xr, h2][-4:] @ W_out + b_out -----------
__global__ __launch_bounds__(256) void k_out(const float* __restrict__ Wout,
                                             const float* __restrict__ bout,
                                             float* __restrict__ out) {
    __shared__ float sX[32][129];
    __shared__ float sW[128][9];
    int tt = blockIdx.y;
    int n0 = blockIdx.x * 32;
    int tid = threadIdx.x;
    for (int i = tid; i < 32 * 64; i += 256) {
        int r = i >> 6, k = i & 63;
        int m = n0 + r;
        sX[r][k] = (m < NN) ? g_xr[((size_t)(TT - 4 + tt) * NN + m) * 64 + k] : 0.f;
        sX[r][64 + k] = (m < NN) ? g_h2last[((size_t)tt * NN + m) * 64 + k] : 0.f;
    }
    for (int i = tid; i < 128 * 8; i += 256) sW[i >> 3][i & 7] = Wout[i];
    __syncthreads();
    int node = tid >> 3, o = tid & 7;
    float acc = bout[o];
    for (int k = 0; k < 128; k++) acc += sX[node][k] * sW[k][o];
    int m = n0 + node;
    if (m < NN) out[((size_t)tt * NN + m) * 8 + o] = acc;
}

// ---------------- launch ----------------------------------------------------------
extern "C" void kernel_launch(void* const* d_in, const int* in_sizes, int n_in,
                              void* d_out, int out_size) {
    const float* x      = (const float*)d_in[0];
    const int*   ei     = (const int*)d_in[1];
    const float* ew     = (const float*)d_in[2];
    const float* sWr    = (const float*)d_in[3];
    const float* sWroot = (const float*)d_in[4];
    const float* sb     = (const float*)d_in[5];
    const float* Wr1    = (const float*)d_in[6];
    const float* Wroot1 = (const float*)d_in[7];
    const float* b1     = (const float*)d_in[8];
    const float* Wr2    = (const float*)d_in[9];
    const float* Wroot2 = (const float*)d_in[10];
    const float* b2     = (const float*)d_in[11];
    const float* Wout   = (const float*)d_in[12];
    const float* bout   = (const float*)d_in[13];
    float* out = (float*)d_out;
    const int* src = ei;
    const int* dst = ei + EE;

    int nsm = 0;
    cudaDeviceGetAttribute(&nsm, cudaDevAttrMultiProcessorCount, 0);
    cudaFuncSetAttribute(k_chain, cudaFuncAttributeMaxDynamicSharedMemorySize,
                         CHAIN_SMEM);
    cudaFuncSetAttribute(k_pre, cudaFuncAttributeMaxDynamicSharedMemorySize,
                         PRE_SMEM);

    // CSR build (per launch — deterministic & stateless)
    k_zero_cursor<<<(NN + 255) / 256, 256>>>();
    k_deg<<<(EE + 255) / 256, 256>>>(dst);
    k_scan<<<1, 1024>>>();
    k_fill<<<(EE + 255) / 256, 256>>>(src, dst, ew);

    // SAGE embedding (exact fp32, f32x2 core)
    dim3 aggGridT(2500, TT);
    k_agg<32><<<aggGridT, 256>>>(0, x);
    k_sage<<<TT * NN / 64, 256>>>(x, sWr, sWroot, sb, out + EMB_OFF);

    // Precompute x-dependent half of all LSTM gates (fp16 mma, persistent)
    k_agg<64><<<aggGridT, 256>>>(1, nullptr);
    k_pre<<<nsm, 512, PRE_SMEM>>>(Wr1, Wroot1, b1, Wr2, Wroot2, b2);

    // Fused persistent chain: both LSTMs, 24 steps, 1 barrier/step
    k_chain<<<nsm, 512, CHAIN_SMEM>>>(Wr1, Wroot1, Wr2, Wroot2, out + C2_OFF);

    k_out<<<dim3(NN / 32, 4), 256>>>(Wout, bout, out + OUT_OFF);
}

// round 7
// speedup vs baseline: 2.4027x; 1.0499x over previous
#include <cuda_runtime.h>
#include <cuda_fp16.h>
#include <math.h>

#define TT 12
#define NN 20000
#define EE 400000
#define FF 32
#define HH 64
#define OO 8

// Output layout (flattened tuple): out[4,N,8] | c2[N,64] | emb[T,N,64]
#define OUT_OFF 0
#define C2_OFF  (4*NN*OO)                 // 640000
#define EMB_OFF (C2_OFF + NN*HH)          // 1920000

#define N_TILES ((NN + 63) / 64)          // 313
#define PRE_TILES (TT * NN / 128)         // 1875

// ---------------- scratch (static device globals; allocation-free at runtime) ----
__device__ int      g_rowptr[NN + 1];
__device__ int      g_cursor[NN];
__device__ int      g_csr_src[EE];
__device__ float    g_csr_w[EE];
__device__ unsigned g_xrh[TT * NN * 32];         // relu(emb) as half2 pairs
__device__ float    g_aggx[TT * NN * FF];        // wmean(x) per t (fp32, emb path)
__device__ unsigned g_aggxrh[TT * NN * 32];      // wmean(xr) as half2 pairs
__device__ unsigned g_preh[2][TT * NN * 128];    // gate pre-contrib, half2 pairs
__device__ unsigned g_hh[2][NN * 32];            // fp16 hidden state (half2 words)
__device__ float    g_c[NN * HH];
__device__ float    g_h2last[4 * NN * HH];       // h2 for last 4 steps (fp32)

// grid barrier state
__device__ unsigned g_bar_count = 0;
__device__ volatile unsigned g_bar_gen = 0;

// ---------------- helpers ----------------------------------------------------------
__device__ __forceinline__ void mma16(float* c, const uint4 a, const uint2 b) {
    asm volatile(
        "mma.sync.aligned.m16n8k16.row.col.f32.f16.f16.f32 "
        "{%0,%1,%2,%3},{%4,%5,%6,%7},{%8,%9},{%0,%1,%2,%3};"
        : "+f"(c[0]), "+f"(c[1]), "+f"(c[2]), "+f"(c[3])
        : "r"(a.x), "r"(a.y), "r"(a.z), "r"(a.w), "r"(b.x), "r"(b.y));
}
__device__ __forceinline__ unsigned h2u(float lo, float hi) {
    __half2 h = __floats2half2_rn(lo, hi);
    return *(unsigned*)&h;
}
__device__ __forceinline__ float2 u2f2(unsigned u) {
    return __half22float2(*(const __half2*)&u);
}
__device__ __forceinline__ unsigned long long pk2(float lo, float hi) {
    unsigned long long r;
    asm("mov.b64 %0, {%1,%2};" : "=l"(r) : "f"(lo), "f"(hi));
    return r;
}
__device__ __forceinline__ void upk2(unsigned long long v, float& lo, float& hi) {
    asm("mov.b64 {%0,%1}, %2;" : "=f"(lo), "=f"(hi) : "l"(v));
}
__device__ __forceinline__ unsigned long long ffma2(unsigned long long a,
                                                    unsigned long long b,
                                                    unsigned long long c) {
    unsigned long long d;
    asm("fma.rn.f32x2 %0, %1, %2, %3;" : "=l"(d) : "l"(a), "l"(b), "l"(c));
    return d;
}
__device__ __forceinline__ unsigned ld_acq(volatile unsigned* p) {
    unsigned v;
    asm volatile("ld.acquire.gpu.u32 %0, [%1];"
                 : "=r"(v) : "l"((const unsigned*)p) : "memory");
    return v;
}
__device__ __forceinline__ void gridbar(unsigned& gen) {
    __syncthreads();
    if (threadIdx.x == 0) {
        __threadfence();
        unsigned t = atomicAdd(&g_bar_count, 1);
        if (t == gridDim.x - 1) {
            g_bar_count = 0;
            __threadfence();
            asm volatile("st.release.gpu.u32 [%0], %1;"
                         :: "l"((unsigned*)&g_bar_gen), "r"(gen + 1) : "memory");
        } else {
            while (ld_acq(&g_bar_gen) != gen + 1) __nanosleep(32);
        }
    }
    gen++;
    __syncthreads();
}

// ---------------- CSR construction ------------------------------------------------
__global__ void k_zero_cursor() {
    int i = blockIdx.x * blockDim.x + threadIdx.x;
    if (i < NN) g_cursor[i] = 0;
}

__global__ void k_deg(const int* __restrict__ dst) {
    int e = blockIdx.x * blockDim.x + threadIdx.x;
    if (e < EE) atomicAdd(&g_cursor[dst[e]], 1);
}

__global__ void k_scan() {
    __shared__ int wsum[32];
    const int CH = 20;
    int tid = threadIdx.x;
    int base = tid * CH;
    int loc[CH];
    int s = 0;
#pragma unroll
    for (int i = 0; i < CH; i++) {
        int idx = base + i;
        int v = (idx < NN) ? g_cursor[idx] : 0;
        loc[i] = s;
        s += v;
    }
    int lane = tid & 31, w = tid >> 5;
    int inc = s;
#pragma unroll
    for (int o = 1; o < 32; o <<= 1) {
        int t = __shfl_up_sync(0xffffffffu, inc, o);
        if (lane >= o) inc += t;
    }
    if (lane == 31) wsum[w] = inc;
    __syncthreads();
    if (w == 0) {
        int v = wsum[lane];
#pragma unroll
        for (int o = 1; o < 32; o <<= 1) {
            int t = __shfl_up_sync(0xffffffffu, v, o);
            if (lane >= o) v += t;
        }
        wsum[lane] = v;
    }
    __syncthreads();
    int excl = inc - s + (w > 0 ? wsum[w - 1] : 0);
#pragma unroll
    for (int i = 0; i < CH; i++) {
        int idx = base + i;
        if (idx < NN) {
            int p = excl + loc[i];
            g_rowptr[idx] = p;
            g_cursor[idx] = p;
        }
    }
    if (tid == 0) g_rowptr[NN] = EE;
}

__global__ void k_fill(const int* __restrict__ src, const int* __restrict__ dst,
                       const float* __restrict__ ew) {
    int e = blockIdx.x * blockDim.x + threadIdx.x;
    if (e < EE) {
        int d = dst[e];
        int pos = atomicAdd(&g_cursor[d], 1);
        g_csr_src[pos] = src[e];
        g_csr_w[pos] = ew[e];
    }
}

// ---------------- wmean of x (fp32, emb path), MLP-4 edge loop, parallel T --------
__global__ void k_aggx(const float* __restrict__ xin) {
    int gw = (blockIdx.x * blockDim.x + threadIdx.x) >> 5;
    int lane = threadIdx.x & 31;
    if (gw >= NN) return;
    size_t toff = (size_t)blockIdx.y * NN * FF;
    const float* __restrict__ in = xin + toff;
    float* __restrict__ out = g_aggx + toff;

    int e0 = g_rowptr[gw], e1 = g_rowptr[gw + 1];
    float acc = 0.f;
    int e = e0;
    for (; e + 4 <= e1; e += 4) {
        int s0 = __ldg(&g_csr_src[e]);
        int s1 = __ldg(&g_csr_src[e + 1]);
        int s2 = __ldg(&g_csr_src[e + 2]);
        int s3 = __ldg(&g_csr_src[e + 3]);
        float w0 = __ldg(&g_csr_w[e]);
        float w1 = __ldg(&g_csr_w[e + 1]);
        float w2 = __ldg(&g_csr_w[e + 2]);
        float w3 = __ldg(&g_csr_w[e + 3]);
        float v0 = __ldg(&in[(size_t)s0 * FF + lane]);
        float v1 = __ldg(&in[(size_t)s1 * FF + lane]);
        float v2 = __ldg(&in[(size_t)s2 * FF + lane]);
        float v3 = __ldg(&in[(size_t)s3 * FF + lane]);
        acc += w0 * v0 + w1 * v1 + w2 * v2 + w3 * v3;
    }
    for (; e < e1; e++) {
        int s = __ldg(&g_csr_src[e]);
        float w = __ldg(&g_csr_w[e]);
        acc += w * __ldg(&in[(size_t)s * FF + lane]);
    }
    out[(size_t)gw * FF + lane] = acc / (float)max(e1 - e0, 1);
}

// ---------------- wmean of xr (fp16 in/out), MLP-4, parallel T --------------------
__global__ void k_aggh() {
    int gw = (blockIdx.x * blockDim.x + threadIdx.x) >> 5;
    int lane = threadIdx.x & 31;
    if (gw >= NN) return;
    size_t toff = (size_t)blockIdx.y * NN * 32;
    const unsigned* __restrict__ in = g_xrh + toff;
    unsigned* __restrict__ out = g_aggxrh + toff;

    int e0 = g_rowptr[gw], e1 = g_rowptr[gw + 1];
    float ax = 0.f, ay = 0.f;
    int e = e0;
    for (; e + 4 <= e1; e += 4) {
        int s0 = __ldg(&g_csr_src[e]);
        int s1 = __ldg(&g_csr_src[e + 1]);
        int s2 = __ldg(&g_csr_src[e + 2]);
        int s3 = __ldg(&g_csr_src[e + 3]);
        float w0 = __ldg(&g_csr_w[e]);
        float w1 = __ldg(&g_csr_w[e + 1]);
        float w2 = __ldg(&g_csr_w[e + 2]);
        float w3 = __ldg(&g_csr_w[e + 3]);
        float2 v0 = u2f2(__ldg(&in[(size_t)s0 * 32 + lane]));
        float2 v1 = u2f2(__ldg(&in[(size_t)s1 * 32 + lane]));
        float2 v2 = u2f2(__ldg(&in[(size_t)s2 * 32 + lane]));
        float2 v3 = u2f2(__ldg(&in[(size_t)s3 * 32 + lane]));
        ax += w0 * v0.x + w1 * v1.x + w2 * v2.x + w3 * v3.x;
        ay += w0 * v0.y + w1 * v1.y + w2 * v2.y + w3 * v3.y;
    }
    for (; e < e1; e++) {
        int s = __ldg(&g_csr_src[e]);
        float w = __ldg(&g_csr_w[e]);
        float2 v = u2f2(__ldg(&in[(size_t)s * 32 + lane]));
        ax += w * v.x;
        ay += w * v.y;
    }
    float inv = 1.f / (float)max(e1 - e0, 1);
    out[(size_t)gw * 32 + lane] = h2u(ax * inv, ay * inv);
}

// ---------------- SAGE (f32x2 core, exact fp32): emb fp32; xrh fp16 ---------------
__global__ __launch_bounds__(256, 2) void k_sage(const float* __restrict__ x,
                                                 const float* __restrict__ Wr,
                                                 const float* __restrict__ Wroot,
                                                 const float* __restrict__ b,
                                                 float* __restrict__ emb) {
    __shared__ float sA[64][33];
    __shared__ float sW[32][66];
    int m0 = blockIdx.x * 64;
    int tid = threadIdx.x;
    int tr = tid / 16, tc = tid % 16;
    unsigned long long acc[4][2];
#pragma unroll
    for (int i = 0; i < 4; i++)
#pragma unroll
        for (int j2 = 0; j2 < 2; j2++) acc[i][j2] = 0ull;
    for (int kb = 0; kb < 2; kb++) {
        const float* Asrc = kb ? x : g_aggx;
        const float* Wsrc = kb ? Wroot : Wr;
        __syncthreads();
        for (int i = tid; i < 64 * 32; i += 256) {
            int r = i >> 5, k = i & 31;
            sA[r][k] = Asrc[(size_t)(m0 + r) * 32 + k];
        }
        for (int i = tid; i < 32 * 64; i += 256) {
            int r = i >> 6, cc = i & 63;
            sW[r][cc] = Wsrc[(size_t)r * 64 + cc];
        }
        __syncthreads();
#pragma unroll
        for (int k = 0; k < 32; k++) {
            unsigned long long a2[4];
#pragma unroll
            for (int i = 0; i < 4; i++) {
                float av = sA[tr * 4 + i][k];
                a2[i] = pk2(av, av);
            }
#pragma unroll
            for (int j2 = 0; j2 < 2; j2++) {
                unsigned long long w2 = *(const unsigned long long*)&sW[k][tc * 4 + j2 * 2];
#pragma unroll
                for (int i = 0; i < 4; i++) acc[i][j2] = ffma2(a2[i], w2, acc[i][j2]);
            }
        }
    }
#pragma unroll
    for (int i = 0; i < 4; i++) {
        int m = m0 + tr * 4 + i;
        size_t mrow = (size_t)m * 64;
#pragma unroll
        for (int j2 = 0; j2 < 2; j2++) {
            float v0, v1;
            upk2(acc[i][j2], v0, v1);
            int c0 = tc * 4 + j2 * 2;
            v0 += b[c0];
            v1 += b[c0 + 1];
            emb[mrow + c0] = v0;
            emb[mrow + c0 + 1] = v1;
            g_xrh[(size_t)m * 32 + (c0 >> 1)] = h2u(fmaxf(v0, 0.f), fmaxf(v1, 0.f));
        }
    }
}

// ---------------- persistent PRE (fp16 mma): both layers, W staged once/SM --------
// preh[L] = [aggxrh|xrh](128 rows/tile) @ [Wr[0:64];Wroot[0:64]](fp16) + b  -> fp16
#define PRE_SMEM ((8 * 32 * 32 * 2 + 8 * 8 * 32 * 4) * 4)
__global__ __launch_bounds__(512, 1) void k_pre(const float* __restrict__ Wr1,
                                                const float* __restrict__ Wroot1,
                                                const float* __restrict__ b1,
                                                const float* __restrict__ Wr2,
                                                const float* __restrict__ Wroot2,
                                                const float* __restrict__ b2) {
    extern __shared__ unsigned smem[];
    unsigned* sW = smem;
    unsigned* sA = smem + 8 * 32 * 32 * 2;
    int tid = threadIdx.x;
    int warp = tid >> 5, lane = tid & 31;
    int wm = warp >> 2, wn = warp & 3;
    int gid = lane >> 2, tig = lane & 3;

    for (int L = 0; L < 2; L++) {
        const float* __restrict__ Wr = L ? Wr2 : Wr1;
        const float* __restrict__ Wroot = L ? Wroot2 : Wroot1;
        const float* __restrict__ bias = L ? b2 : b1;
        unsigned* __restrict__ preh = g_preh[L];
        __syncthreads();
        for (int i = tid; i < 64 * 256; i += 512) {
            int k2 = i >> 8, n = i & 255;
            int k = k2 * 2;
            float v0, v1;
            if (k < 64) {
                v0 = Wr[(size_t)k * 256 + n];
                v1 = Wr[(size_t)(k + 1) * 256 + n];
            } else {
                v0 = Wroot[(size_t)(k - 64) * 256 + n];
                v1 = Wroot[(size_t)(k - 63) * 256 + n];
            }
            int kc = k2 >> 3, breg = (k2 >> 2) & 1;
            int bl = (n & 7) * 4 + (k2 & 3);
            sW[((kc * 32 + (n >> 3)) * 32 + bl) * 2 + breg] = h2u(v0, v1);
        }
        __syncthreads();

        for (int tile = blockIdx.x; tile < PRE_TILES; tile += gridDim.x) {
            int m0 = tile * 128;
            __syncthreads();
            // stage A: direct u32 copies (already half2 pairs)
            for (int i = tid; i < 128 * 64; i += 512) {
                int r = i >> 6, c2 = i & 63;
                size_t m32 = (size_t)(m0 + r) * 32;
                unsigned u = (c2 < 32) ? g_aggxrh[m32 + c2] : g_xrh[m32 + (c2 - 32)];
                int mf = r >> 4, kc = c2 >> 3;
                int reg = ((c2 >> 2) & 1) * 2 + ((r >> 3) & 1);
                int al = (r & 7) * 4 + (c2 & 3);
                sA[((mf * 8 + kc) * 32 + al) * 4 + reg] = u;
            }
            __syncthreads();
            float acc[2][4][2][4];
#pragma unroll
            for (int mf = 0; mf < 2; mf++)
#pragma unroll
                for (int g = 0; g < 4; g++)
#pragma unroll
                    for (int hh = 0; hh < 2; hh++)
#pragma unroll
                        for (int q = 0; q < 4; q++) acc[mf][g][hh][q] = 0.f;
#pragma unroll
            for (int kc = 0; kc < 8; kc++) {
                uint4 a[2];
#pragma unroll
                for (int mf = 0; mf < 2; mf++)
                    a[mf] = ((const uint4*)sA)[((wm * 2 + mf) * 8 + kc) * 32 + lane];
#pragma unroll
                for (int g = 0; g < 4; g++)
#pragma unroll
                    for (int hh = 0; hh < 2; hh++) {
                        int n8 = g * 8 + wn * 2 + hh;
                        uint2 b = ((const uint2*)sW)[(kc * 32 + n8) * 32 + lane];
#pragma unroll
                        for (int mf = 0; mf < 2; mf++)
                            mma16(acc[mf][g][hh], a[mf], b);
                    }
            }
#pragma unroll
            for (int mf = 0; mf < 2; mf++)
#pragma unroll
                for (int rr = 0; rr < 2; rr++) {
                    int m = m0 + wm * 32 + mf * 16 + gid + rr * 8;
#pragma unroll
                    for (int g = 0; g < 4; g++)
#pragma unroll
                        for (int hh = 0; hh < 2; hh++) {
                            int n0 = g * 64 + wn * 16 + hh * 8 + tig * 2;
                            float2 bv = *(const float2*)&bias[n0];
                            float vx = acc[mf][g][hh][rr * 2 + 0] + bv.x;
                            float vy = acc[mf][g][hh][rr * 2 + 1] + bv.y;
                            preh[(size_t)m * 128 + (n0 >> 1)] = h2u(vx, vy);
                        }
                }
        }
    }
}

// ---------------- persistent fused LSTM chain (fp16 h/pre, MLP-4 gather) ----------
#define CHAIN_SMEM (160 * 1024)
__global__ __launch_bounds__(512, 1) void k_chain(const float* __restrict__ Wr1,
                                                  const float* __restrict__ Wroot1,
                                                  const float* __restrict__ Wr2,
                                                  const float* __restrict__ Wroot2,
                                                  float* __restrict__ outC2) {
    extern __shared__ unsigned smem[];
    unsigned* sW = smem;                      // 16384 u32
    unsigned* sA = smem + 8 * 32 * 32 * 2;    // 4096 u32
    int tid = threadIdx.x;
    int warp = tid >> 5, lane = tid & 31;
    int wm = warp >> 3, wn = warp & 7;
    int gid = lane >> 2, tig = lane & 3;
    unsigned gen = g_bar_gen;

    for (int i = blockIdx.x * 512 + tid; i < NN * 32; i += gridDim.x * 512)
        g_hh[0][i] = 0u;
    for (int i = blockIdx.x * 512 + tid; i < NN * HH; i += gridDim.x * 512)
        g_c[i] = 0.f;
    gridbar(gen);

    int par = 0;
    for (int L = 0; L < 2; L++) {
        const float* __restrict__ Wr = L ? Wr2 : Wr1;
        const float* __restrict__ Wroot = L ? Wroot2 : Wroot1;
        for (int i = tid; i < 64 * 256; i += 512) {
            int k2 = i >> 8, n = i & 255;
            int k = k2 * 2;
            float v0, v1;
            if (k < 64) {
                v0 = Wr[(size_t)(64 + k) * 256 + n];
                v1 = Wr[(size_t)(65 + k) * 256 + n];
            } else {
                v0 = Wroot[(size_t)k * 256 + n];
                v1 = Wroot[(size_t)(k + 1) * 256 + n];
            }
            int kc = k2 >> 3, breg = (k2 >> 2) & 1;
            int bl = (n & 7) * 4 + (k2 & 3);
            sW[((kc * 32 + (n >> 3)) * 32 + bl) * 2 + breg] = h2u(v0, v1);
        }
        __syncthreads();
        const unsigned* __restrict__ preL = g_preh[L];

        for (int t = 0; t < TT; t++) {
            const unsigned* __restrict__ hin = g_hh[par];
            unsigned* __restrict__ hout = g_hh[par ^ 1];
            const unsigned* __restrict__ pre = preL + (size_t)t * NN * 128;
            int store = (L == 1 && t >= TT - 4) ? (t - (TT - 4)) : -1;

            for (int tile = blockIdx.x; tile < N_TILES; tile += gridDim.x) {
                int m0 = tile * 64;
                __syncthreads();
#pragma unroll
                for (int rq = 0; rq < 4; rq++) {
                    int r = warp * 4 + rq;
                    int m = m0 + r;
                    unsigned aggu = 0u, hu = 0u;
                    if (m < NN) {
                        int e0 = g_rowptr[m], e1 = g_rowptr[m + 1];
                        float ax = 0.f, ay = 0.f;
                        int e = e0;
                        for (; e + 4 <= e1; e += 4) {
                            int s0 = __ldg(&g_csr_src[e]);
                            int s1 = __ldg(&g_csr_src[e + 1]);
                            int s2 = __ldg(&g_csr_src[e + 2]);
                            int s3 = __ldg(&g_csr_src[e + 3]);
                            float w0 = __ldg(&g_csr_w[e]);
                            float w1 = __ldg(&g_csr_w[e + 1]);
                            float w2 = __ldg(&g_csr_w[e + 2]);
                            float w3 = __ldg(&g_csr_w[e + 3]);
                            float2 v0 = u2f2(__ldg(&hin[(size_t)s0 * 32 + lane]));
                            float2 v1 = u2f2(__ldg(&hin[(size_t)s1 * 32 + lane]));
                            float2 v2 = u2f2(__ldg(&hin[(size_t)s2 * 32 + lane]));
                            float2 v3 = u2f2(__ldg(&hin[(size_t)s3 * 32 + lane]));
                            ax += w0 * v0.x + w1 * v1.x + w2 * v2.x + w3 * v3.x;
                            ay += w0 * v0.y + w1 * v1.y + w2 * v2.y + w3 * v3.y;
                        }
                        for (; e < e1; e++) {
                            int s = __ldg(&g_csr_src[e]);
                            float w = __ldg(&g_csr_w[e]);
                            float2 v = u2f2(__ldg(&hin[(size_t)s * 32 + lane]));
                            ax += w * v.x;
                            ay += w * v.y;
                        }
                        float inv = 1.f / (float)max(e1 - e0, 1);
                        aggu = h2u(ax * inv, ay * inv);
                        hu = hin[(size_t)m * 32 + lane];
                    }
                    int mf = r >> 4;
                    int reg_base = (r >> 3) & 1;
                    int al = (r & 7) * 4 + (lane & 3);
                    int regc = ((lane >> 2) & 1) * 2 + reg_base;
                    int kcA = lane >> 3;
                    sA[((mf * 8 + kcA) * 32 + al) * 4 + regc] = aggu;
                    sA[((mf * 8 + 4 + kcA) * 32 + al) * 4 + regc] = hu;
                }
                __syncthreads();
                float acc[2][4][4];
#pragma unroll
                for (int mf = 0; mf < 2; mf++)
#pragma unroll
                    for (int g = 0; g < 4; g++)
#pragma unroll
                        for (int q = 0; q < 4; q++) acc[mf][g][q] = 0.f;
#pragma unroll
                for (int kc = 0; kc < 8; kc++) {
                    uint4 a[2];
#pragma unroll
                    for (int mf = 0; mf < 2; mf++)
                        a[mf] = ((const uint4*)sA)[((wm * 2 + mf) * 8 + kc) * 32 + lane];
#pragma unroll
                    for (int g = 0; g < 4; g++) {
                        int n8 = g * 8 + wn;
                        uint2 b = ((const uint2*)sW)[(kc * 32 + n8) * 32 + lane];
#pragma unroll
                        for (int mf = 0; mf < 2; mf++)
                            mma16(acc[mf][g], a[mf], b);
                    }
                }
#pragma unroll
                for (int mf = 0; mf < 2; mf++)
#pragma unroll
                    for (int rr = 0; rr < 2; rr++) {
                        int m = m0 + wm * 32 + mf * 16 + gid + rr * 8;
                        if (m >= NN) continue;
                        int hc = wn * 8 + tig * 2;
                        size_t pb = (size_t)m * 128 + (hc >> 1);
                        float2 pi = u2f2(pre[pb]);
                        float2 pf = u2f2(pre[pb + 32]);
                        float2 pg = u2f2(pre[pb + 64]);
                        float2 po = u2f2(pre[pb + 96]);
                        size_t hb = (size_t)m * 64 + hc;
                        float2 cold = *(const float2*)&g_c[hb];
                        float gi0 = acc[mf][0][rr * 2 + 0] + pi.x;
                        float gi1 = acc[mf][0][rr * 2 + 1] + pi.y;
                        float gf0 = acc[mf][1][rr * 2 + 0] + pf.x;
                        float gf1 = acc[mf][1][rr * 2 + 1] + pf.y;
                        float gg0 = acc[mf][2][rr * 2 + 0] + pg.x;
                        float gg1 = acc[mf][2][rr * 2 + 1] + pg.y;
                        float go0 = acc[mf][3][rr * 2 + 0] + po.x;
                        float go1 = acc[mf][3][rr * 2 + 1] + po.y;
                        float si0 = __fdividef(1.f, 1.f + __expf(-gi0));
                        float si1 = __fdividef(1.f, 1.f + __expf(-gi1));
                        float sf0 = __fdividef(1.f, 1.f + __expf(-gf0));
                        float sf1 = __fdividef(1.f, 1.f + __expf(-gf1));
                        float so0 = __fdividef(1.f, 1.f + __expf(-go0));
                        float so1 = __fdividef(1.f, 1.f + __expf(-go1));
                        float2 cn, hn;
                        cn.x = sf0 * cold.x + si0 * tanhf(gg0);
                        cn.y = sf1 * cold.y + si1 * tanhf(gg1);
                        hn.x = so0 * tanhf(cn.x);
                        hn.y = so1 * tanhf(cn.y);
                        *(float2*)&g_c[hb] = cn;
                        hout[(size_t)m * 32 + (hc >> 1)] = h2u(hn.x, hn.y);
                        if (store >= 0)
                            *(float2*)&g_h2last[(size_t)store * NN * 64 + hb] = hn;
                    }
            }
            gridbar(gen);
            par ^= 1;
        }
        __syncthreads();
    }

    for (int i = blockIdx.x * 512 + tid; i < NN * HH; i += gridDim.x * 512)
        outC2[i] = g_c[i];
}

// ---------------- final projection: out = [relu(emb), h2][-4:] @ W_out + b_out ----
__global__ __launch_bounds__(256) void k_out(const float* __restrict__ emb,
                                             const float* __restrict__ Wout,
                                             const float* __restrict__ bout,
                                             float* __restrict__ out) {
    __shared__ float sX[32][129];
    __shared__ float sW[128][9];
    int tt = blockIdx.y;
    int n0 = blockIdx.x * 32;
    int tid = threadIdx.x;
    for (int i = tid; i < 32 * 64; i += 256) {
        int r = i >> 6, k = i & 63;
        int m = n0 + r;
        sX[r][k] = (m < NN)
            ? fmaxf(emb[((size_t)(TT - 4 + tt) * NN + m) * 64 + k], 0.f) : 0.f;
        sX[r][64 + k] = (m < NN) ? g_h2last[((size_t)tt * NN + m) * 64 + k] : 0.f;
    }
    for (int i = tid; i < 128 * 8; i += 256) sW[i >> 3][i & 7] = Wout[i];
    __syncthreads();
    int node = tid >> 3, o = tid & 7;
    float acc = bout[o];
    for (int k = 0; k < 128; k++) acc += sX[node][k] * sW[k][o];
    int m = n0 + node;
    if (m < NN) out[((size_t)tt * NN + m) * 8 + o] = acc;
}

// ---------------- launch ----------------------------------------------------------
extern "C" void kernel_launch(void* const* d_in, const int* in_sizes, int n_in,
                              void* d_out, int out_size) {
    const float* x      = (const float*)d_in[0];
    const int*   ei     = (const int*)d_in[1];
    const float* ew     = (const float*)d_in[2];
    const float* sWr    = (const float*)d_in[3];
    const float* sWroot = (const float*)d_in[4];
    const float* sb     = (const float*)d_in[5];
    const float* Wr1    = (const float*)d_in[6];
    const float* Wroot1 = (const float*)d_in[7];
    const float* b1     = (const float*)d_in[8];
    const float* Wr2    = (const float*)d_in[9];
    const float* Wroot2 = (const float*)d_in[10];
    const float* b2     = (const float*)d_in[11];
    const float* Wout   = (const float*)d_in[12];
    const float* bout   = (const float*)d_in[13];
    float* out = (float*)d_out;
    const int* src = ei;
    const int* dst = ei + EE;

    int nsm = 0;
    cudaDeviceGetAttribute(&nsm, cudaDevAttrMultiProcessorCount, 0);
    cudaFuncSetAttribute(k_chain, cudaFuncAttributeMaxDynamicSharedMemorySize,
                         CHAIN_SMEM);
    cudaFuncSetAttribute(k_pre, cudaFuncAttributeMaxDynamicSharedMemorySize,
                         PRE_SMEM);

    // CSR build
    k_zero_cursor<<<(NN + 255) / 256, 256>>>();
    k_deg<<<(EE + 255) / 256, 256>>>(dst);
    k_scan<<<1, 1024>>>();
    k_fill<<<(EE + 255) / 256, 256>>>(src, dst, ew);

    // SAGE embedding (exact fp32 -> emb; fp16 xr)
    dim3 aggGridT(2500, TT);
    k_aggx<<<aggGridT, 256>>>(x);
    k_sage<<<TT * NN / 64, 256>>>(x, sWr, sWroot, sb, out + EMB_OFF);

    // x-dependent gate halves (fp16 agg + fp16 mma + fp16 pre)
    k_aggh<<<aggGridT, 256>>>();
    k_pre<<<nsm, 512, PRE_SMEM>>>(Wr1, Wroot1, b1, Wr2, Wroot2, b2);

    // Fused persistent chain
    k_chain<<<nsm, 512, CHAIN_SMEM>>>(Wr1, Wroot1, Wr2, Wroot2, out + C2_OFF);

    k_out<<<dim3(NN / 32, 4), 256>>>(out + EMB_OFF, Wout, bout, out + OUT_OFF);
}